// round 10
// baseline (speedup 1.0000x reference)
#include <cuda_runtime.h>
#include <cuda_fp16.h>
#include <math.h>
#include <stdint.h>

#define D_MODEL 1024
#define NHEAD 8
#define CHEAD 128
#define BATCH 4
#define SEQ 2048
#define ROWS (BATCH*SEQ)   /* 8192 */

// ---------------- scratch (module-static device memory; no runtime allocs) ---
__device__ __align__(128) __half g_yh [ROWS * D_MODEL];
__device__ __align__(128) __half g_q  [BATCH * NHEAD * SEQ * CHEAD]; // [b][h][n][c]
__device__ __align__(128) __half g_k  [BATCH * NHEAD * SEQ * CHEAD]; // [b][h][n][c]
__device__ __align__(128) __half g_v  [BATCH * NHEAD * CHEAD * SEQ]; // [b][h][c][n]
__device__ __align__(128) float  g_att[ROWS * D_MODEL];
__device__ __align__(128) __half g_h1 [ROWS * 4 * D_MODEL];
#define WH3_OFF 0
#define WH1_OFF (3072*1024)
#define WH2_OFF (WH1_OFF + 4096*1024)
__device__ __align__(128) __half g_wh [WH2_OFF + 1024*4096];

// ------------------------------------------------------------ PTX helpers ---
__device__ __forceinline__ uint32_t smem_u32(const void* p) {
    uint32_t r;
    asm("{ .reg .u64 t; cvta.to.shared.u64 t, %1; cvt.u32.u64 %0, t; }"
        : "=r"(r) : "l"(p));
    return r;
}
__device__ __forceinline__ void cp16(uint32_t dst, const void* src) {
    asm volatile("cp.async.ca.shared.global [%0], [%1], 16;\n" :: "r"(dst), "l"(src));
}
__device__ __forceinline__ void cp_commit() {
    asm volatile("cp.async.commit_group;\n" ::: "memory");
}
__device__ __forceinline__ void cp_wait1() {
    asm volatile("cp.async.wait_group 1;\n" ::: "memory");
}
__device__ __forceinline__ void ldsm4(uint32_t* r, uint32_t addr) {
    asm volatile("ldmatrix.sync.aligned.m8n8.x4.shared.b16 {%0,%1,%2,%3}, [%4];"
        : "=r"(r[0]), "=r"(r[1]), "=r"(r[2]), "=r"(r[3]) : "r"(addr));
}
__device__ __forceinline__ void mma16(float* c, const uint32_t* a, const uint32_t* b) {
    asm volatile(
        "mma.sync.aligned.m16n8k16.row.col.f32.f16.f16.f32 "
        "{%0,%1,%2,%3}, {%4,%5,%6,%7}, {%8,%9}, {%0,%1,%2,%3};"
        : "+f"(c[0]), "+f"(c[1]), "+f"(c[2]), "+f"(c[3])
        : "r"(a[0]), "r"(a[1]), "r"(a[2]), "r"(a[3]), "r"(b[0]), "r"(b[1]));
}

// ------------------------------------------- weight transpose+convert -------
__global__ void __launch_bounds__(256) tc_kernel(const float* __restrict__ in,
                                                 __half* __restrict__ out,
                                                 int K, int N) {
    __shared__ float t[32][33];
    const int nb = blockIdx.x * 32, kb = blockIdx.y * 32;
    const int tx = threadIdx.x, ty = threadIdx.y;
    #pragma unroll
    for (int i = 0; i < 32; i += 8)
        t[ty + i][tx] = in[(size_t)(kb + ty + i) * N + nb + tx];
    __syncthreads();
    #pragma unroll
    for (int i = 0; i < 32; i += 8)
        out[(size_t)(nb + ty + i) * K + kb + tx] = __float2half(t[tx][ty + i]);
}

// ---------------------------------------------------------------- LayerNorm --
__global__ void __launch_bounds__(256) ln_kernel(const float* __restrict__ in,
                                                 const float* __restrict__ gamma,
                                                 const float* __restrict__ beta,
                                                 __half* __restrict__ out) {
    const int row = blockIdx.x;
    const float* p = in + (size_t)row * D_MODEL;
    float s = 0.f, sq = 0.f;
    for (int i = threadIdx.x; i < D_MODEL; i += 256) {
        float v = p[i];
        s += v; sq += v * v;
    }
    #pragma unroll
    for (int o = 16; o; o >>= 1) {
        s  += __shfl_xor_sync(0xffffffffu, s,  o);
        sq += __shfl_xor_sync(0xffffffffu, sq, o);
    }
    __shared__ float ws[8], wq[8];
    int w = threadIdx.x >> 5, l = threadIdx.x & 31;
    if (l == 0) { ws[w] = s; wq[w] = sq; }
    __syncthreads();
    if (threadIdx.x == 0) {
        float ts = 0.f, tq = 0.f;
        #pragma unroll
        for (int i = 0; i < 8; i++) { ts += ws[i]; tq += wq[i]; }
        ws[0] = ts; wq[0] = tq;
    }
    __syncthreads();
    const float mu  = ws[0] * (1.f / D_MODEL);
    const float var = wq[0] * (1.f / D_MODEL) - mu * mu;
    const float rs  = rsqrtf(var + 1e-3f);
    __half* po = out + (size_t)row * D_MODEL;
    for (int i = threadIdx.x; i < D_MODEL; i += 256)
        po[i] = __float2half((p[i] - mu) * rs * gamma[i] + beta[i]);
}

// ------------------------------------------------ FP16 mma.sync GEMM --------
// CTA 128x256 (MxN), BK=32, 8 warps (2 row x 4 col), warp tile 64x64.
// 3-stage cp.async, ldmatrix fragment loads, one __syncthreads per iter.
#define GST 40
#define A_HALVES (128*GST)
#define B_HALVES (256*GST)
#define ST_HALVES (A_HALVES + B_HALVES)
#define GEMM_SMEM_BYTES (3*ST_HALVES*2)   /* 92160 B */

__device__ __forceinline__ void g_load_stage(const __half* __restrict__ Ag,
                                             const __half* __restrict__ Bg,
                                             int K, uint32_t aBase, uint32_t bBase,
                                             int k0, int tid) {
    #pragma unroll
    for (int p = 0; p < 2; p++) {           // A: 128 rows x 32 halves
        const int id = p * 256 + tid;
        const int r = id >> 2, c8 = (id & 3) * 8;
        cp16(aBase + (r * GST + c8) * 2, Ag + (size_t)r * K + k0 + c8);
    }
    #pragma unroll
    for (int p = 0; p < 4; p++) {           // B: 256 rows x 32 halves
        const int id = p * 256 + tid;
        const int r = id >> 2, c8 = (id & 3) * 8;
        cp16(bBase + (r * GST + c8) * 2, Bg + (size_t)r * K + k0 + c8);
    }
    cp_commit();
}

template<int EPI>
__global__ void __launch_bounds__(256, 1) mgemm_kernel(const __half* __restrict__ A,
                                                       const __half* __restrict__ WT,
                                                       const float* __restrict__ bias,
                                                       const float* __restrict__ res,
                                                       void* __restrict__ CoutV,
                                                       int M, int N, int K) {
    extern __shared__ __half hsm[];

    const int tid = threadIdx.x;
    const int wid = tid >> 5, lane = tid & 31;
    const int wm = wid & 1, wn = wid >> 1;    // 2 x 4 warp grid, 64x64 tiles
    const int lq = lane >> 2, lr = lane & 3;
    const int bx = blockIdx.x, by = blockIdx.y;

    const __half* Ag = A  + (size_t)(by * 128) * K;
    const __half* Bg = WT + (size_t)(bx * 256) * K;

    uint32_t aBase[3], bBase[3];
    #pragma unroll
    for (int s = 0; s < 3; s++) {
        aBase[s] = smem_u32(hsm + s * ST_HALVES);
        bBase[s] = smem_u32(hsm + s * ST_HALVES + A_HALVES);
    }

    const int aRow = lane & 15, aK = (lane >> 4) * 8;
    const int bRow = (lane & 7) + ((lane >> 4) << 3), bK = ((lane >> 3) & 1) * 8;

    float acc[4][8][4];
    #pragma unroll
    for (int f = 0; f < 4; f++)
        #pragma unroll
        for (int g = 0; g < 8; g++)
            #pragma unroll
            for (int e = 0; e < 4; e++) acc[f][g][e] = 0.f;

    const int iters = K >> 5;
    g_load_stage(Ag, Bg, K, aBase[0], bBase[0], 0, tid);
    g_load_stage(Ag, Bg, K, aBase[1], bBase[1], 32, tid);

    int s = 0;
    for (int it = 0; it < iters; it++) {
        cp_wait1();
        __syncthreads();
        if (it + 2 < iters) {
            int ns = s + 2; if (ns >= 3) ns -= 3;
            g_load_stage(Ag, Bg, K, aBase[ns], bBase[ns], (it + 2) << 5, tid);
        }

        #pragma unroll
        for (int kk = 0; kk < 2; kk++) {
            const int c0 = kk * 16;
            uint32_t a[4][4], b[8][2];
            #pragma unroll
            for (int f = 0; f < 4; f++)
                ldsm4(a[f], aBase[s] + ((wm * 64 + f * 16 + aRow) * GST + c0 + aK) * 2);
            #pragma unroll
            for (int g2 = 0; g2 < 4; g2++) {
                uint32_t t4[4];
                ldsm4(t4, bBase[s] + ((wn * 64 + g2 * 16 + bRow) * GST + c0 + bK) * 2);
                b[g2 * 2][0] = t4[0];     b[g2 * 2][1] = t4[1];
                b[g2 * 2 + 1][0] = t4[2]; b[g2 * 2 + 1][1] = t4[3];
            }
            #pragma unroll
            for (int f = 0; f < 4; f++)
                #pragma unroll
                for (int g = 0; g < 8; g++)
                    mma16(acc[f][g], a[f], b[g]);
        }
        s = (s == 2) ? 0 : s + 1;
    }

    #pragma unroll
    for (int f = 0; f < 4; f++) {
        #pragma unroll
        for (int g = 0; g < 8; g++) {
            const int row0 = by * 128 + wm * 64 + f * 16 + lq;
            const int col0 = bx * 256 + wn * 64 + g * 8 + lr * 2;
            #pragma unroll
            for (int h = 0; h < 2; h++) {
                const int row = row0 + h * 8;
                float v0 = acc[f][g][h * 2 + 0] + bias[col0];
                float v1 = acc[f][g][h * 2 + 1] + bias[col0 + 1];
                if (EPI == 0) {
                    v0 = fmaxf(v0, 0.f); v1 = fmaxf(v1, 0.f);
                    #pragma unroll
                    for (int e = 0; e < 2; e++) {
                        const float xv = e ? v1 : v0;
                        const int col = col0 + e;
                        const int cc  = col / 24;
                        const int rem = col - cc * 24;
                        const int hh  = rem / 3;
                        const int ii  = rem - hh * 3;
                        const int bb  = row >> 11;
                        const int nn  = row & 2047;
                        size_t dst;
                        __half* dptr;
                        if (ii == 2) {
                            dptr = g_v;
                            dst = (((size_t)bb * NHEAD + hh) * CHEAD + cc) * SEQ + nn;
                        } else {
                            dptr = (ii == 0) ? g_q : g_k;
                            dst = (((size_t)bb * NHEAD + hh) * SEQ + nn) * CHEAD + cc;
                        }
                        dptr[dst] = __float2half(xv);
                    }
                } else if (EPI == 1) {
                    __half2 o = __floats2half2_rn(fmaxf(v0, 0.f), fmaxf(v1, 0.f));
                    *(__half2*)&((__half*)CoutV)[(size_t)row * N + col0] = o;
                } else {
                    float* Cout = (float*)CoutV;
                    const float2 rr = *(const float2*)&res[(size_t)row * N + col0];
                    float2 o; o.x = v0 + rr.x; o.y = v1 + rr.y;
                    *(float2*)&Cout[(size_t)row * N + col0] = o;
                }
            }
        }
    }
}

// ------------------------------------------------ fp16 tensor Attention -----
#define AQ_ST 136
#define AV_ST 88
#define AP_ST 72
#define AS_ST 68
#define ATTN_F32 (64*AS_ST + 192)
#define ATTN_H   (64*AQ_ST + 64*AQ_ST + 128*AV_ST + 64*AP_ST)
#define ATTN_SMEM_BYTES (ATTN_F32*4 + ATTN_H*2)

__global__ void __launch_bounds__(256) attn_kernel(const float* __restrict__ x,
                                                   float* __restrict__ out) {
    extern __shared__ float smf[];
    float* sS = smf;
    float* sM = sS + 64 * AS_ST;
    float* sL = sM + 64;
    float* sA = sL + 64;
    __half* sQ  = (__half*)(smf + ATTN_F32);
    __half* sK  = sQ  + 64 * AQ_ST;
    __half* sVt = sK  + 64 * AQ_ST;
    __half* sP  = sVt + 128 * AV_ST;

    const int qb = blockIdx.x, h = blockIdx.y, b = blockIdx.z;
    const int tid = threadIdx.x;
    const int wid = tid >> 5, lane = tid & 31;
    const int lq = lane >> 2, lr = lane & 3;
    const int wm = wid & 3, wn = wid >> 2;

    const uint32_t qB  = smem_u32(sQ);
    const uint32_t kB  = smem_u32(sK);
    const uint32_t vB  = smem_u32(sVt);
    const uint32_t pB  = smem_u32(sP);
    const int aRow = lane & 15, aK = (lane >> 4) * 8;
    const int bRow = (lane & 7) + ((lane >> 4) << 3), bK = ((lane >> 3) & 1) * 8;

    const size_t bh  = ((size_t)b * NHEAD + h) * SEQ;
    const __half* Qg = g_q + (bh + (size_t)qb * 64) * CHEAD;
    const __half* Vb = g_v + ((size_t)b * NHEAD + h) * CHEAD * SEQ;

    for (int idx = tid; idx < 64 * 16; idx += 256) {
        const int r = idx >> 4, c8 = (idx & 15) * 8;
        *(uint4*)&sQ[r * AQ_ST + c8] = *(const uint4*)&Qg[r * 128 + c8];
    }
    if (tid < 64) { sM[tid] = -1e30f; sL[tid] = 0.f; }

    float oacc[8][4];
    #pragma unroll
    for (int f = 0; f < 8; f++)
        #pragma unroll
        for (int e = 0; e < 4; e++) oacc[f][e] = 0.f;

    for (int kt = 0; kt < SEQ / 64; kt++) {
        __syncthreads();
        const __half* Kg = g_k + (bh + (size_t)kt * 64) * CHEAD;
        for (int idx = tid; idx < 64 * 16; idx += 256) {
            const int r = idx >> 4, c8 = (idx & 15) * 8;
            *(uint4*)&sK[r * AQ_ST + c8] = *(const uint4*)&Kg[r * 128 + c8];
        }
        for (int idx = tid; idx < 128 * 8; idx += 256) {
            const int c = idx >> 3, k8 = (idx & 7) * 8;
            *(uint4*)&sVt[c * AV_ST + k8] =
                *(const uint4*)&Vb[(size_t)c * SEQ + kt * 64 + k8];
        }
        __syncthreads();

        // ---- S = Q @ K^T ---------------------------------------------------
        float sc[4][4];
        #pragma unroll
        for (int g = 0; g < 4; g++)
            #pragma unroll
            for (int e = 0; e < 4; e++) sc[g][e] = 0.f;
        #pragma unroll
        for (int kk = 0; kk < 8; kk++) {
            const int c0 = kk * 16;
            uint32_t a[4], bfr[4][2];
            ldsm4(a, qB + ((wm * 16 + aRow) * AQ_ST + c0 + aK) * 2);
            #pragma unroll
            for (int g2 = 0; g2 < 2; g2++) {
                uint32_t t4[4];
                ldsm4(t4, kB + ((wn * 32 + g2 * 16 + bRow) * AQ_ST + c0 + bK) * 2);
                bfr[g2 * 2][0] = t4[0];     bfr[g2 * 2][1] = t4[1];
                bfr[g2 * 2 + 1][0] = t4[2]; bfr[g2 * 2 + 1][1] = t4[3];
            }
            #pragma unroll
            for (int g = 0; g < 4; g++)
                mma16(sc[g], a, bfr[g]);
        }
        {
            const int r0 = wm * 16 + lq;
            #pragma unroll
            for (int g = 0; g < 4; g++) {
                const int c0 = wn * 32 + g * 8 + lr * 2;
                *(float2*)&sS[r0 * AS_ST + c0] =
                    make_float2(sc[g][0] * 0.125f, sc[g][1] * 0.125f);
                *(float2*)&sS[(r0 + 8) * AS_ST + c0] =
                    make_float2(sc[g][2] * 0.125f, sc[g][3] * 0.125f);
            }
        }
        __syncthreads();

        // ---- online softmax -------------------------------------------------
        {
            const int row = tid >> 2, seg = (tid & 3) * 16;
            float* rp = sS + row * AS_ST + seg;
            __half* pp = sP + row * AP_ST + seg;
            float mx = -1e30f;
            #pragma unroll
            for (int j = 0; j < 16; j++) mx = fmaxf(mx, rp[j]);
            mx = fmaxf(mx, __shfl_xor_sync(0xffffffffu, mx, 1));
            mx = fmaxf(mx, __shfl_xor_sync(0xffffffffu, mx, 2));
            const float mo = sM[row];
            const float mn = fmaxf(mo, mx);
            float l = 0.f;
            #pragma unroll
            for (int j = 0; j < 8; j++) {
                const float p0 = __expf(rp[2*j]   - mn);
                const float p1 = __expf(rp[2*j+1] - mn);
                l += p0 + p1;
                *(__half2*)&pp[2*j] = __floats2half2_rn(p0, p1);
            }
            l += __shfl_xor_sync(0xffffffffu, l, 1);
            l += __shfl_xor_sync(0xffffffffu, l, 2);
            if ((tid & 3) == 0) {
                const float alpha = __expf(mo - mn);
                sA[row] = alpha;
                sL[row] = sL[row] * alpha + l;
                sM[row] = mn;
            }
        }
        __syncthreads();

        // ---- O = O*alpha + P @ V --------------------------------------------
        const float al0 = sA[wm * 16 + lq];
        const float al1 = sA[wm * 16 + lq + 8];
        #pragma unroll
        for (int f = 0; f < 8; f++) {
            oacc[f][0] *= al0; oacc[f][1] *= al0;
            oacc[f][2] *= al1; oacc[f][3] *= al1;
        }
        #pragma unroll
        for (int kk = 0; kk < 4; kk++) {
            const int c0 = kk * 16;
            uint32_t a[4], bfr[8][2];
            ldsm4(a, pB + ((wm * 16 + aRow) * AP_ST + c0 + aK) * 2);
            #pragma unroll
            for (int f2 = 0; f2 < 4; f2++) {
                uint32_t t4[4];
                ldsm4(t4, vB + ((wn * 64 + f2 * 16 + bRow) * AV_ST + c0 + bK) * 2);
                bfr[f2 * 2][0] = t4[0];     bfr[f2 * 2][1] = t4[1];
                bfr[f2 * 2 + 1][0] = t4[2]; bfr[f2 * 2 + 1][1] = t4[3];
            }
            #pragma unroll
            for (int f = 0; f < 8; f++)
                mma16(oacc[f], a, bfr[f]);
        }
    }

    // ------------------------------ epilogue --------------------------------
    const int r0 = wm * 16 + lq;
    const float inv0 = 1.f / sL[r0];
    const float inv1 = 1.f / sL[r0 + 8];
    const int q0 = qb * 64 + r0;
    #pragma unroll
    for (int f = 0; f < 8; f++) {
        const int col = wn * 64 + f * 8 + lr * 2;
        const size_t b0 = ((size_t)b * SEQ + q0) * D_MODEL + h * CHEAD + col;
        const size_t b1 = ((size_t)b * SEQ + q0 + 8) * D_MODEL + h * CHEAD + col;
        const float2 x0 = *(const float2*)&x[b0];
        const float2 x1 = *(const float2*)&x[b1];
        float2 o0, o1;
        o0.x = oacc[f][0] * inv0 + x0.x; o0.y = oacc[f][1] * inv0 + x0.y;
        o1.x = oacc[f][2] * inv1 + x1.x; o1.y = oacc[f][3] * inv1 + x1.y;
        *(float2*)&out[b0] = o0;
        *(float2*)&out[b1] = o1;
    }
}

// ------------------------------------------------------------------ launch --
extern "C" void kernel_launch(void* const* d_in, const int* in_sizes, int n_in,
                              void* d_out, int out_size) {
    const float* x    = (const float*)d_in[0];
    const float* ln_g = (const float*)d_in[1];
    const float* ln_b = (const float*)d_in[2];
    const float* w3   = (const float*)d_in[3];
    const float* b3   = (const float*)d_in[4];
    const float* w1   = (const float*)d_in[5];
    const float* b1   = (const float*)d_in[6];
    const float* w2   = (const float*)d_in[7];
    const float* b2   = (const float*)d_in[8];
    float* out = (float*)d_out;

    __half *yh, *h1, *wh;
    float *att;
    cudaGetSymbolAddress((void**)&yh,  g_yh);
    cudaGetSymbolAddress((void**)&att, g_att);
    cudaGetSymbolAddress((void**)&h1,  g_h1);
    cudaGetSymbolAddress((void**)&wh,  g_wh);

    cudaFuncSetAttribute(attn_kernel, cudaFuncAttributeMaxDynamicSharedMemorySize,
                         ATTN_SMEM_BYTES);
    cudaFuncSetAttribute(mgemm_kernel<0>, cudaFuncAttributeMaxDynamicSharedMemorySize,
                         GEMM_SMEM_BYTES);
    cudaFuncSetAttribute(mgemm_kernel<1>, cudaFuncAttributeMaxDynamicSharedMemorySize,
                         GEMM_SMEM_BYTES);
    cudaFuncSetAttribute(mgemm_kernel<2>, cudaFuncAttributeMaxDynamicSharedMemorySize,
                         GEMM_SMEM_BYTES);

    tc_kernel<<<dim3(3072/32, 1024/32), dim3(32, 8)>>>(w3, wh + WH3_OFF, 1024, 3072);
    tc_kernel<<<dim3(4096/32, 1024/32), dim3(32, 8)>>>(w1, wh + WH1_OFF, 1024, 4096);
    tc_kernel<<<dim3(1024/32, 4096/32), dim3(32, 8)>>>(w2, wh + WH2_OFF, 4096, 1024);

    ln_kernel<<<ROWS, 256>>>(x, ln_g, ln_b, yh);
    mgemm_kernel<0><<<dim3(3072/256, ROWS/128), 256, GEMM_SMEM_BYTES>>>(
        yh, wh + WH3_OFF, b3, nullptr, nullptr, ROWS, 3072, 1024);
    attn_kernel<<<dim3(SEQ/64, NHEAD, BATCH), 256, ATTN_SMEM_BYTES>>>(x, att);
    ln_kernel<<<ROWS, 256>>>(att, ln_g, ln_b, yh);
    mgemm_kernel<1><<<dim3(4096/256, ROWS/128), 256, GEMM_SMEM_BYTES>>>(
        yh, wh + WH1_OFF, b1, nullptr, h1, ROWS, 4096, 1024);
    mgemm_kernel<2><<<dim3(1024/256, ROWS/128), 256, GEMM_SMEM_BYTES>>>(
        h1, wh + WH2_OFF, b2, att, out, ROWS, 1024, 4096);
}

// round 11
// speedup vs baseline: 1.2796x; 1.2796x over previous
#include <cuda_runtime.h>
#include <cuda_fp16.h>
#include <math.h>
#include <stdint.h>

#define D_MODEL 1024
#define NHEAD 8
#define CHEAD 128
#define BATCH 4
#define SEQ 2048
#define ROWS (BATCH*SEQ)   /* 8192 */

// ---------------- scratch (module-static device memory; no runtime allocs) ---
__device__ __align__(128) __half g_yh [ROWS * D_MODEL];
__device__ __align__(128) __half g_q  [BATCH * NHEAD * SEQ * CHEAD]; // [b][h][n][c]
__device__ __align__(128) __half g_k  [BATCH * NHEAD * SEQ * CHEAD]; // [b][h][n][c]
__device__ __align__(128) __half g_v  [BATCH * NHEAD * CHEAD * SEQ]; // [b][h][c][n]
__device__ __align__(128) float  g_att[ROWS * D_MODEL];
__device__ __align__(128) __half g_h1 [ROWS * 4 * D_MODEL];
#define WH3_OFF 0
#define WH1_OFF (3072*1024)
#define WH2_OFF (WH1_OFF + 4096*1024)
__device__ __align__(128) __half g_wh [WH2_OFF + 1024*4096];

// ------------------------------------------------------------ PTX helpers ---
__device__ __forceinline__ uint32_t smem_u32(const void* p) {
    uint32_t r;
    asm("{ .reg .u64 t; cvta.to.shared.u64 t, %1; cvt.u32.u64 %0, t; }"
        : "=r"(r) : "l"(p));
    return r;
}
__device__ __forceinline__ void cp16(uint32_t dst, const void* src) {
    asm volatile("cp.async.ca.shared.global [%0], [%1], 16;\n" :: "r"(dst), "l"(src));
}
__device__ __forceinline__ void cp_commit() {
    asm volatile("cp.async.commit_group;\n" ::: "memory");
}
__device__ __forceinline__ void cp_wait1() {
    asm volatile("cp.async.wait_group 1;\n" ::: "memory");
}
__device__ __forceinline__ void ldsm4(uint32_t* r, uint32_t addr) {
    asm volatile("ldmatrix.sync.aligned.m8n8.x4.shared.b16 {%0,%1,%2,%3}, [%4];"
        : "=r"(r[0]), "=r"(r[1]), "=r"(r[2]), "=r"(r[3]) : "r"(addr));
}
__device__ __forceinline__ void mma16(float* c, const uint32_t* a, const uint32_t* b) {
    asm volatile(
        "mma.sync.aligned.m16n8k16.row.col.f32.f16.f16.f32 "
        "{%0,%1,%2,%3}, {%4,%5,%6,%7}, {%8,%9}, {%0,%1,%2,%3};"
        : "+f"(c[0]), "+f"(c[1]), "+f"(c[2]), "+f"(c[3])
        : "r"(a[0]), "r"(a[1]), "r"(a[2]), "r"(a[3]), "r"(b[0]), "r"(b[1]));
}
__device__ __forceinline__ uint32_t h2u(__half2 h) {
    return *(uint32_t*)&h;
}

// ------------------------------------------- weight transpose+convert -------
__global__ void __launch_bounds__(256) tc_kernel(const float* __restrict__ in,
                                                 __half* __restrict__ out,
                                                 int K, int N) {
    __shared__ float t[32][33];
    const int nb = blockIdx.x * 32, kb = blockIdx.y * 32;
    const int tx = threadIdx.x, ty = threadIdx.y;
    #pragma unroll
    for (int i = 0; i < 32; i += 8)
        t[ty + i][tx] = in[(size_t)(kb + ty + i) * N + nb + tx];
    __syncthreads();
    #pragma unroll
    for (int i = 0; i < 32; i += 8)
        out[(size_t)(nb + ty + i) * K + kb + tx] = __float2half(t[tx][ty + i]);
}

// ---------------------------------------------------------------- LayerNorm --
__global__ void __launch_bounds__(256) ln_kernel(const float* __restrict__ in,
                                                 const float* __restrict__ gamma,
                                                 const float* __restrict__ beta,
                                                 __half* __restrict__ out) {
    const int row = blockIdx.x;
    const float* p = in + (size_t)row * D_MODEL;
    float s = 0.f, sq = 0.f;
    for (int i = threadIdx.x; i < D_MODEL; i += 256) {
        float v = p[i];
        s += v; sq += v * v;
    }
    #pragma unroll
    for (int o = 16; o; o >>= 1) {
        s  += __shfl_xor_sync(0xffffffffu, s,  o);
        sq += __shfl_xor_sync(0xffffffffu, sq, o);
    }
    __shared__ float ws[8], wq[8];
    int w = threadIdx.x >> 5, l = threadIdx.x & 31;
    if (l == 0) { ws[w] = s; wq[w] = sq; }
    __syncthreads();
    if (threadIdx.x == 0) {
        float ts = 0.f, tq = 0.f;
        #pragma unroll
        for (int i = 0; i < 8; i++) { ts += ws[i]; tq += wq[i]; }
        ws[0] = ts; wq[0] = tq;
    }
    __syncthreads();
    const float mu  = ws[0] * (1.f / D_MODEL);
    const float var = wq[0] * (1.f / D_MODEL) - mu * mu;
    const float rs  = rsqrtf(var + 1e-3f);
    __half* po = out + (size_t)row * D_MODEL;
    for (int i = threadIdx.x; i < D_MODEL; i += 256)
        po[i] = __float2half((p[i] - mu) * rs * gamma[i] + beta[i]);
}

// ------------------------------------------------ FP16 mma.sync GEMM --------
#define GST 40
#define GS_HALVES (128*GST)
#define GEMM_SMEM_BYTES (6*GS_HALVES*2)   /* 61440 B */

__device__ __forceinline__ void g_load_stage(const __half* __restrict__ Ag,
                                             const __half* __restrict__ Bg,
                                             int K, uint32_t aBase, uint32_t bBase,
                                             int k0, int tid) {
    #pragma unroll
    for (int p = 0; p < 2; p++) {
        const int id = p * 256 + tid;
        const int r = id >> 2, c8 = (id & 3) * 8;
        cp16(aBase + (r * GST + c8) * 2, Ag + (size_t)r * K + k0 + c8);
        cp16(bBase + (r * GST + c8) * 2, Bg + (size_t)r * K + k0 + c8);
    }
    cp_commit();
}

template<int EPI>
__global__ void __launch_bounds__(256, 2) mgemm_kernel(const __half* __restrict__ A,
                                                       const __half* __restrict__ WT,
                                                       const float* __restrict__ bias,
                                                       const float* __restrict__ res,
                                                       void* __restrict__ CoutV,
                                                       int M, int N, int K) {
    extern __shared__ __half hsm[];

    const int tid = threadIdx.x;
    const int wid = tid >> 5, lane = tid & 31;
    const int wm = wid & 1, wn = wid >> 1;
    const int lq = lane >> 2, lr = lane & 3;
    const int bx = blockIdx.x, by = blockIdx.y;

    const __half* Ag = A  + (size_t)(by * 128) * K;
    const __half* Bg = WT + (size_t)(bx * 128) * K;

    uint32_t aBase[3], bBase[3];
    #pragma unroll
    for (int s = 0; s < 3; s++) {
        aBase[s] = smem_u32(hsm + (2 * s)     * GS_HALVES);
        bBase[s] = smem_u32(hsm + (2 * s + 1) * GS_HALVES);
    }

    const int aRow = lane & 15, aK = (lane >> 4) * 8;
    const int bRow = (lane & 7) + ((lane >> 4) << 3), bK = ((lane >> 3) & 1) * 8;

    float acc[4][4][4];
    #pragma unroll
    for (int f = 0; f < 4; f++)
        #pragma unroll
        for (int g = 0; g < 4; g++)
            #pragma unroll
            for (int e = 0; e < 4; e++) acc[f][g][e] = 0.f;

    const int iters = K >> 5;
    g_load_stage(Ag, Bg, K, aBase[0], bBase[0], 0, tid);
    g_load_stage(Ag, Bg, K, aBase[1], bBase[1], 32, tid);

    int s = 0;
    for (int it = 0; it < iters; it++) {
        cp_wait1();
        __syncthreads();
        if (it + 2 < iters) {
            int ns = s + 2; if (ns >= 3) ns -= 3;
            g_load_stage(Ag, Bg, K, aBase[ns], bBase[ns], (it + 2) << 5, tid);
        }

        #pragma unroll
        for (int kk = 0; kk < 2; kk++) {
            const int c0 = kk * 16;
            uint32_t a[4][4], b[4][2];
            #pragma unroll
            for (int f = 0; f < 4; f++)
                ldsm4(a[f], aBase[s] + ((wm * 64 + f * 16 + aRow) * GST + c0 + aK) * 2);
            #pragma unroll
            for (int g2 = 0; g2 < 2; g2++) {
                uint32_t t4[4];
                ldsm4(t4, bBase[s] + ((wn * 32 + g2 * 16 + bRow) * GST + c0 + bK) * 2);
                b[g2 * 2][0] = t4[0];     b[g2 * 2][1] = t4[1];
                b[g2 * 2 + 1][0] = t4[2]; b[g2 * 2 + 1][1] = t4[3];
            }
            #pragma unroll
            for (int f = 0; f < 4; f++)
                #pragma unroll
                for (int g = 0; g < 4; g++)
                    mma16(acc[f][g], a[f], b[g]);
        }
        s = (s == 2) ? 0 : s + 1;
    }

    #pragma unroll
    for (int f = 0; f < 4; f++) {
        #pragma unroll
        for (int g = 0; g < 4; g++) {
            const int row0 = by * 128 + wm * 64 + f * 16 + lq;
            const int col0 = bx * 128 + wn * 32 + g * 8 + lr * 2;
            #pragma unroll
            for (int h = 0; h < 2; h++) {
                const int row = row0 + h * 8;
                float v0 = acc[f][g][h * 2 + 0] + bias[col0];
                float v1 = acc[f][g][h * 2 + 1] + bias[col0 + 1];
                if (EPI == 0) {
                    v0 = fmaxf(v0, 0.f); v1 = fmaxf(v1, 0.f);
                    #pragma unroll
                    for (int e = 0; e < 2; e++) {
                        const float xv = e ? v1 : v0;
                        const int col = col0 + e;
                        const int cc  = col / 24;
                        const int rem = col - cc * 24;
                        const int hh  = rem / 3;
                        const int ii  = rem - hh * 3;
                        const int bb  = row >> 11;
                        const int nn  = row & 2047;
                        size_t dst;
                        __half* dptr;
                        if (ii == 2) {
                            dptr = g_v;
                            dst = (((size_t)bb * NHEAD + hh) * CHEAD + cc) * SEQ + nn;
                        } else {
                            dptr = (ii == 0) ? g_q : g_k;
                            dst = (((size_t)bb * NHEAD + hh) * SEQ + nn) * CHEAD + cc;
                        }
                        dptr[dst] = __float2half(xv);
                    }
                } else if (EPI == 1) {
                    __half2 o = __floats2half2_rn(fmaxf(v0, 0.f), fmaxf(v1, 0.f));
                    *(__half2*)&((__half*)CoutV)[(size_t)row * N + col0] = o;
                } else {
                    float* Cout = (float*)CoutV;
                    const float2 rr = *(const float2*)&res[(size_t)row * N + col0];
                    float2 o; o.x = v0 + rr.x; o.y = v1 + rr.y;
                    *(float2*)&Cout[(size_t)row * N + col0] = o;
                }
            }
        }
    }
}

// ---------------------------------------- FA2-style fp16 tensor Attention ---
// Q-tile 128/CTA, KV-tile 64. Warp w owns rows 16w..16w+15 and the full 64-wide
// KV tile: softmax in registers (quad shfl); P packed straight into A-frags.
#define AQ_ST 136
#define AV_ST 72
#define ATTN_H   (128*AQ_ST + 64*AQ_ST + 128*AV_ST)
#define ATTN_SMEM_BYTES (ATTN_H*2)   /* 70656 B */

__global__ void __launch_bounds__(256) attn_kernel(const float* __restrict__ x,
                                                   float* __restrict__ out) {
    extern __shared__ __half hsm[];
    __half* sQ  = hsm;                  // [128][136]
    __half* sK  = sQ  + 128 * AQ_ST;    // [64][136]
    __half* sVt = sK  + 64  * AQ_ST;    // [128][72]  ([c][kv])

    const int qb = blockIdx.x, h = blockIdx.y, b = blockIdx.z;
    const int tid = threadIdx.x;
    const int wid = tid >> 5, lane = tid & 31;
    const int lq = lane >> 2, lr = lane & 3;

    const uint32_t qB = smem_u32(sQ);
    const uint32_t kB = smem_u32(sK);
    const uint32_t vB = smem_u32(sVt);
    const int aRow = lane & 15, aK = (lane >> 4) * 8;
    const int bRow = (lane & 7) + ((lane >> 4) << 3), bK = ((lane >> 3) & 1) * 8;

    const size_t bh  = ((size_t)b * NHEAD + h) * SEQ;
    const __half* Qg = g_q + (bh + (size_t)qb * 128) * CHEAD;
    const __half* Vb = g_v + ((size_t)b * NHEAD + h) * CHEAD * SEQ;

    for (int idx = tid; idx < 128 * 16; idx += 256) {
        const int r = idx >> 4, c8 = (idx & 15) * 8;
        *(uint4*)&sQ[r * AQ_ST + c8] = *(const uint4*)&Qg[r * 128 + c8];
    }

    float m0 = -1e30f, m1 = -1e30f, l0 = 0.f, l1 = 0.f;
    float oacc[16][4];
    #pragma unroll
    for (int t = 0; t < 16; t++)
        #pragma unroll
        for (int e = 0; e < 4; e++) oacc[t][e] = 0.f;

    for (int kt = 0; kt < SEQ / 64; kt++) {
        __syncthreads();
        const __half* Kg = g_k + (bh + (size_t)kt * 64) * CHEAD;
        for (int idx = tid; idx < 64 * 16; idx += 256) {
            const int r = idx >> 4, c8 = (idx & 15) * 8;
            *(uint4*)&sK[r * AQ_ST + c8] = *(const uint4*)&Kg[r * 128 + c8];
        }
        for (int idx = tid; idx < 128 * 8; idx += 256) {
            const int c = idx >> 3, k8 = (idx & 7) * 8;
            *(uint4*)&sVt[c * AV_ST + k8] =
                *(const uint4*)&Vb[(size_t)c * SEQ + kt * 64 + k8];
        }
        __syncthreads();

        // ---- S = Q @ K^T : warp tile 16 x 64 -------------------------------
        float sc[8][4];
        #pragma unroll
        for (int g = 0; g < 8; g++)
            #pragma unroll
            for (int e = 0; e < 4; e++) sc[g][e] = 0.f;
        #pragma unroll
        for (int kk = 0; kk < 8; kk++) {
            const int c0 = kk * 16;
            uint32_t a[4], bfr[8][2];
            ldsm4(a, qB + ((wid * 16 + aRow) * AQ_ST + c0 + aK) * 2);
            #pragma unroll
            for (int g4 = 0; g4 < 4; g4++) {
                uint32_t t4[4];
                ldsm4(t4, kB + ((g4 * 16 + bRow) * AQ_ST + c0 + bK) * 2);
                bfr[g4 * 2][0] = t4[0];     bfr[g4 * 2][1] = t4[1];
                bfr[g4 * 2 + 1][0] = t4[2]; bfr[g4 * 2 + 1][1] = t4[3];
            }
            #pragma unroll
            for (int g = 0; g < 8; g++)
                mma16(sc[g], a, bfr[g]);
        }

        // ---- register online softmax (rows lq, lq+8) -----------------------
        float mx0 = -1e30f, mx1 = -1e30f;
        #pragma unroll
        for (int g = 0; g < 8; g++) {
            mx0 = fmaxf(mx0, fmaxf(sc[g][0], sc[g][1]));
            mx1 = fmaxf(mx1, fmaxf(sc[g][2], sc[g][3]));
        }
        mx0 = fmaxf(mx0, __shfl_xor_sync(0xffffffffu, mx0, 1));
        mx0 = fmaxf(mx0, __shfl_xor_sync(0xffffffffu, mx0, 2));
        mx1 = fmaxf(mx1, __shfl_xor_sync(0xffffffffu, mx1, 1));
        mx1 = fmaxf(mx1, __shfl_xor_sync(0xffffffffu, mx1, 2));
        mx0 *= 0.125f; mx1 *= 0.125f;
        const float mn0 = fmaxf(m0, mx0), mn1 = fmaxf(m1, mx1);
        const float al0 = __expf(m0 - mn0), al1 = __expf(m1 - mn1);
        m0 = mn0; m1 = mn1;

        uint32_t aP[4][4];
        float sum0 = 0.f, sum1 = 0.f;
        #pragma unroll
        for (int g = 0; g < 8; g++) {
            const float p0 = __expf(fmaf(sc[g][0], 0.125f, -mn0));
            const float p1 = __expf(fmaf(sc[g][1], 0.125f, -mn0));
            const float p2 = __expf(fmaf(sc[g][2], 0.125f, -mn1));
            const float p3 = __expf(fmaf(sc[g][3], 0.125f, -mn1));
            sum0 += p0 + p1; sum1 += p2 + p3;
            const int kk = g >> 1, hi = (g & 1) * 2;
            aP[kk][hi]     = h2u(__floats2half2_rn(p0, p1));
            aP[kk][hi + 1] = h2u(__floats2half2_rn(p2, p3));
        }
        sum0 += __shfl_xor_sync(0xffffffffu, sum0, 1);
        sum0 += __shfl_xor_sync(0xffffffffu, sum0, 2);
        sum1 += __shfl_xor_sync(0xffffffffu, sum1, 1);
        sum1 += __shfl_xor_sync(0xffffffffu, sum1, 2);
        l0 = l0 * al0 + sum0;
        l1 = l1 * al1 + sum1;

        // A-frag register order: a0=(row lq,k lo), a1=(row lq+8,k lo),
        // a2=(row lq,k hi), a3=(row lq+8,k hi) → reorder aP in place:
        // currently aP[kk] = {p_lo_r0, p_lo_r8(from tile 2kk: p2,p3), ...}
        // Built above as: aP[kk][0]=tile2kk rows(lq) cols lo, aP[kk][1]=tile2kk rows(lq+8),
        //                 aP[kk][2]=tile2kk+1 rows(lq) (k hi), aP[kk][3]=tile2kk+1 rows(lq+8).
        // This matches {a0,a1,a2,a3} exactly.

        // ---- O = O*alpha + P @ V : warp tile 16 x 128 ------------------------
        #pragma unroll
        for (int t = 0; t < 16; t++) {
            oacc[t][0] *= al0; oacc[t][1] *= al0;
            oacc[t][2] *= al1; oacc[t][3] *= al1;
        }
        #pragma unroll
        for (int kk = 0; kk < 4; kk++) {
            const int c0 = kk * 16;
            uint32_t bfr[16][2];
            #pragma unroll
            for (int f4 = 0; f4 < 8; f4++) {
                uint32_t t4[4];
                ldsm4(t4, vB + ((f4 * 16 + bRow) * AV_ST + c0 + bK) * 2);
                bfr[f4 * 2][0] = t4[0];     bfr[f4 * 2][1] = t4[1];
                bfr[f4 * 2 + 1][0] = t4[2]; bfr[f4 * 2 + 1][1] = t4[3];
            }
            #pragma unroll
            for (int t = 0; t < 16; t++)
                mma16(oacc[t], aP[kk], bfr[t]);
        }
    }

    // ------------------------------ epilogue --------------------------------
    const float inv0 = 1.f / l0, inv1 = 1.f / l1;
    const int q0 = qb * 128 + wid * 16 + lq;
    #pragma unroll
    for (int t = 0; t < 16; t++) {
        const int col = t * 8 + lr * 2;
        const size_t b0 = ((size_t)b * SEQ + q0) * D_MODEL + h * CHEAD + col;
        const size_t b1 = ((size_t)b * SEQ + q0 + 8) * D_MODEL + h * CHEAD + col;
        const float2 x0 = *(const float2*)&x[b0];
        const float2 x1 = *(const float2*)&x[b1];
        float2 o0, o1;
        o0.x = oacc[t][0] * inv0 + x0.x; o0.y = oacc[t][1] * inv0 + x0.y;
        o1.x = oacc[t][2] * inv1 + x1.x; o1.y = oacc[t][3] * inv1 + x1.y;
        *(float2*)&out[b0] = o0;
        *(float2*)&out[b1] = o1;
    }
}

// ------------------------------------------------------------------ launch --
extern "C" void kernel_launch(void* const* d_in, const int* in_sizes, int n_in,
                              void* d_out, int out_size) {
    const float* x    = (const float*)d_in[0];
    const float* ln_g = (const float*)d_in[1];
    const float* ln_b = (const float*)d_in[2];
    const float* w3   = (const float*)d_in[3];
    const float* b3   = (const float*)d_in[4];
    const float* w1   = (const float*)d_in[5];
    const float* b1   = (const float*)d_in[6];
    const float* w2   = (const float*)d_in[7];
    const float* b2   = (const float*)d_in[8];
    float* out = (float*)d_out;

    __half *yh, *h1, *wh;
    float *att;
    cudaGetSymbolAddress((void**)&yh,  g_yh);
    cudaGetSymbolAddress((void**)&att, g_att);
    cudaGetSymbolAddress((void**)&h1,  g_h1);
    cudaGetSymbolAddress((void**)&wh,  g_wh);

    cudaFuncSetAttribute(attn_kernel, cudaFuncAttributeMaxDynamicSharedMemorySize,
                         ATTN_SMEM_BYTES);
    cudaFuncSetAttribute(mgemm_kernel<0>, cudaFuncAttributeMaxDynamicSharedMemorySize,
                         GEMM_SMEM_BYTES);
    cudaFuncSetAttribute(mgemm_kernel<1>, cudaFuncAttributeMaxDynamicSharedMemorySize,
                         GEMM_SMEM_BYTES);
    cudaFuncSetAttribute(mgemm_kernel<2>, cudaFuncAttributeMaxDynamicSharedMemorySize,
                         GEMM_SMEM_BYTES);

    tc_kernel<<<dim3(3072/32, 1024/32), dim3(32, 8)>>>(w3, wh + WH3_OFF, 1024, 3072);
    tc_kernel<<<dim3(4096/32, 1024/32), dim3(32, 8)>>>(w1, wh + WH1_OFF, 1024, 4096);
    tc_kernel<<<dim3(1024/32, 4096/32), dim3(32, 8)>>>(w2, wh + WH2_OFF, 4096, 1024);

    ln_kernel<<<ROWS, 256>>>(x, ln_g, ln_b, yh);
    mgemm_kernel<0><<<dim3(3072/128, ROWS/128), 256, GEMM_SMEM_BYTES>>>(
        yh, wh + WH3_OFF, b3, nullptr, nullptr, ROWS, 3072, 1024);
    attn_kernel<<<dim3(SEQ/128, NHEAD, BATCH), 256, ATTN_SMEM_BYTES>>>(x, att);
    ln_kernel<<<ROWS, 256>>>(att, ln_g, ln_b, yh);
    mgemm_kernel<1><<<dim3(4096/128, ROWS/128), 256, GEMM_SMEM_BYTES>>>(
        yh, wh + WH1_OFF, b1, nullptr, h1, ROWS, 4096, 1024);
    mgemm_kernel<2><<<dim3(1024/128, ROWS/128), 256, GEMM_SMEM_BYTES>>>(
        h1, wh + WH2_OFF, b2, att, out, ROWS, 1024, 4096);
}

// round 12
// speedup vs baseline: 1.3083x; 1.0224x over previous
#include <cuda_runtime.h>
#include <cuda_fp16.h>
#include <math.h>
#include <stdint.h>

#define D_MODEL 1024
#define NHEAD 8
#define CHEAD 128
#define BATCH 4
#define SEQ 2048
#define ROWS (BATCH*SEQ)   /* 8192 */

// ---------------- scratch (module-static device memory; no runtime allocs) ---
__device__ __align__(128) __half g_yh [ROWS * D_MODEL];
__device__ __align__(128) __half g_q  [BATCH * NHEAD * SEQ * CHEAD]; // [b][h][n][c]
__device__ __align__(128) __half g_k  [BATCH * NHEAD * SEQ * CHEAD]; // [b][h][n][c]
__device__ __align__(128) __half g_v  [BATCH * NHEAD * CHEAD * SEQ]; // [b][h][c][n]
__device__ __align__(128) float  g_att[ROWS * D_MODEL];
__device__ __align__(128) __half g_h1 [ROWS * 4 * D_MODEL];
#define WH3_OFF 0
#define WH1_OFF (3072*1024)
#define WH2_OFF (WH1_OFF + 4096*1024)
__device__ __align__(128) __half g_wh [WH2_OFF + 1024*4096];

// ------------------------------------------------------------ PTX helpers ---
__device__ __forceinline__ uint32_t smem_u32(const void* p) {
    uint32_t r;
    asm("{ .reg .u64 t; cvta.to.shared.u64 t, %1; cvt.u32.u64 %0, t; }"
        : "=r"(r) : "l"(p));
    return r;
}
__device__ __forceinline__ void cp16(uint32_t dst, const void* src) {
    asm volatile("cp.async.ca.shared.global [%0], [%1], 16;\n" :: "r"(dst), "l"(src));
}
__device__ __forceinline__ void cp_commit() {
    asm volatile("cp.async.commit_group;\n" ::: "memory");
}
__device__ __forceinline__ void cp_wait1() {
    asm volatile("cp.async.wait_group 1;\n" ::: "memory");
}
__device__ __forceinline__ void ldsm4(uint32_t* r, uint32_t addr) {
    asm volatile("ldmatrix.sync.aligned.m8n8.x4.shared.b16 {%0,%1,%2,%3}, [%4];"
        : "=r"(r[0]), "=r"(r[1]), "=r"(r[2]), "=r"(r[3]) : "r"(addr));
}
__device__ __forceinline__ void mma16(float* c, const uint32_t* a, const uint32_t* b) {
    asm volatile(
        "mma.sync.aligned.m16n8k16.row.col.f32.f16.f16.f32 "
        "{%0,%1,%2,%3}, {%4,%5,%6,%7}, {%8,%9}, {%0,%1,%2,%3};"
        : "+f"(c[0]), "+f"(c[1]), "+f"(c[2]), "+f"(c[3])
        : "r"(a[0]), "r"(a[1]), "r"(a[2]), "r"(a[3]), "r"(b[0]), "r"(b[1]));
}
__device__ __forceinline__ uint32_t h2u(__half2 h) {
    return *(uint32_t*)&h;
}

// ------------------------------------------- weight transpose+convert -------
__global__ void __launch_bounds__(256) tc_kernel(const float* __restrict__ in,
                                                 __half* __restrict__ out,
                                                 int K, int N) {
    __shared__ float t[32][33];
    const int nb = blockIdx.x * 32, kb = blockIdx.y * 32;
    const int tx = threadIdx.x, ty = threadIdx.y;
    #pragma unroll
    for (int i = 0; i < 32; i += 8)
        t[ty + i][tx] = in[(size_t)(kb + ty + i) * N + nb + tx];
    __syncthreads();
    #pragma unroll
    for (int i = 0; i < 32; i += 8)
        out[(size_t)(nb + ty + i) * K + kb + tx] = __float2half(t[tx][ty + i]);
}

// ---------------------------------------------------------------- LayerNorm --
__global__ void __launch_bounds__(256) ln_kernel(const float* __restrict__ in,
                                                 const float* __restrict__ gamma,
                                                 const float* __restrict__ beta,
                                                 __half* __restrict__ out) {
    const int row = blockIdx.x;
    const float* p = in + (size_t)row * D_MODEL;
    float s = 0.f, sq = 0.f;
    for (int i = threadIdx.x; i < D_MODEL; i += 256) {
        float v = p[i];
        s += v; sq += v * v;
    }
    #pragma unroll
    for (int o = 16; o; o >>= 1) {
        s  += __shfl_xor_sync(0xffffffffu, s,  o);
        sq += __shfl_xor_sync(0xffffffffu, sq, o);
    }
    __shared__ float ws[8], wq[8];
    int w = threadIdx.x >> 5, l = threadIdx.x & 31;
    if (l == 0) { ws[w] = s; wq[w] = sq; }
    __syncthreads();
    if (threadIdx.x == 0) {
        float ts = 0.f, tq = 0.f;
        #pragma unroll
        for (int i = 0; i < 8; i++) { ts += ws[i]; tq += wq[i]; }
        ws[0] = ts; wq[0] = tq;
    }
    __syncthreads();
    const float mu  = ws[0] * (1.f / D_MODEL);
    const float var = wq[0] * (1.f / D_MODEL) - mu * mu;
    const float rs  = rsqrtf(var + 1e-3f);
    __half* po = out + (size_t)row * D_MODEL;
    for (int i = threadIdx.x; i < D_MODEL; i += 256)
        po[i] = __float2half((p[i] - mu) * rs * gamma[i] + beta[i]);
}

// ------------------------------------------------ FP16 mma.sync GEMM --------
// CTA 128x128, BK=64, 8 warps (2x4), warp tile 64x32. 3-stage cp.async,
// ldmatrix, one __syncthreads per iter. smem 110592 B -> 2 CTA/SM.
#define GST 72
#define GS_HALVES (128*GST)
#define GEMM_SMEM_BYTES (6*GS_HALVES*2)   /* 110592 B */

__device__ __forceinline__ void g_load_stage(const __half* __restrict__ Ag,
                                             const __half* __restrict__ Bg,
                                             int K, uint32_t aBase, uint32_t bBase,
                                             int k0, int tid) {
    #pragma unroll
    for (int p = 0; p < 4; p++) {
        const int id = p * 256 + tid;          // 0..1023 : 128 rows x 8 chunks
        const int r = id >> 3, c8 = (id & 7) * 8;
        cp16(aBase + (r * GST + c8) * 2, Ag + (size_t)r * K + k0 + c8);
        cp16(bBase + (r * GST + c8) * 2, Bg + (size_t)r * K + k0 + c8);
    }
    cp_commit();
}

template<int EPI>
__global__ void __launch_bounds__(256, 2) mgemm_kernel(const __half* __restrict__ A,
                                                       const __half* __restrict__ WT,
                                                       const float* __restrict__ bias,
                                                       const float* __restrict__ res,
                                                       void* __restrict__ CoutV,
                                                       int M, int N, int K) {
    extern __shared__ __half hsm[];

    const int tid = threadIdx.x;
    const int wid = tid >> 5, lane = tid & 31;
    const int wm = wid & 1, wn = wid >> 1;
    const int lq = lane >> 2, lr = lane & 3;
    const int bx = blockIdx.x, by = blockIdx.y;

    const __half* Ag = A  + (size_t)(by * 128) * K;
    const __half* Bg = WT + (size_t)(bx * 128) * K;

    uint32_t aBase[3], bBase[3];
    #pragma unroll
    for (int s = 0; s < 3; s++) {
        aBase[s] = smem_u32(hsm + (2 * s)     * GS_HALVES);
        bBase[s] = smem_u32(hsm + (2 * s + 1) * GS_HALVES);
    }

    const int aRow = lane & 15, aK = (lane >> 4) * 8;
    const int bRow = (lane & 7) + ((lane >> 4) << 3), bK = ((lane >> 3) & 1) * 8;

    float acc[4][4][4];
    #pragma unroll
    for (int f = 0; f < 4; f++)
        #pragma unroll
        for (int g = 0; g < 4; g++)
            #pragma unroll
            for (int e = 0; e < 4; e++) acc[f][g][e] = 0.f;

    const int iters = K >> 6;
    g_load_stage(Ag, Bg, K, aBase[0], bBase[0], 0, tid);
    g_load_stage(Ag, Bg, K, aBase[1], bBase[1], 64, tid);

    int s = 0;
    for (int it = 0; it < iters; it++) {
        cp_wait1();
        __syncthreads();
        if (it + 2 < iters) {
            int ns = s + 2; if (ns >= 3) ns -= 3;
            g_load_stage(Ag, Bg, K, aBase[ns], bBase[ns], (it + 2) << 6, tid);
        }

        #pragma unroll
        for (int kk = 0; kk < 4; kk++) {
            const int c0 = kk * 16;
            uint32_t a[4][4], b[4][2];
            #pragma unroll
            for (int f = 0; f < 4; f++)
                ldsm4(a[f], aBase[s] + ((wm * 64 + f * 16 + aRow) * GST + c0 + aK) * 2);
            #pragma unroll
            for (int g2 = 0; g2 < 2; g2++) {
                uint32_t t4[4];
                ldsm4(t4, bBase[s] + ((wn * 32 + g2 * 16 + bRow) * GST + c0 + bK) * 2);
                b[g2 * 2][0] = t4[0];     b[g2 * 2][1] = t4[1];
                b[g2 * 2 + 1][0] = t4[2]; b[g2 * 2 + 1][1] = t4[3];
            }
            #pragma unroll
            for (int f = 0; f < 4; f++)
                #pragma unroll
                for (int g = 0; g < 4; g++)
                    mma16(acc[f][g], a[f], b[g]);
        }
        s = (s == 2) ? 0 : s + 1;
    }

    #pragma unroll
    for (int f = 0; f < 4; f++) {
        #pragma unroll
        for (int g = 0; g < 4; g++) {
            const int row0 = by * 128 + wm * 64 + f * 16 + lq;
            const int col0 = bx * 128 + wn * 32 + g * 8 + lr * 2;
            #pragma unroll
            for (int h = 0; h < 2; h++) {
                const int row = row0 + h * 8;
                float v0 = acc[f][g][h * 2 + 0] + bias[col0];
                float v1 = acc[f][g][h * 2 + 1] + bias[col0 + 1];
                if (EPI == 0) {
                    v0 = fmaxf(v0, 0.f); v1 = fmaxf(v1, 0.f);
                    #pragma unroll
                    for (int e = 0; e < 2; e++) {
                        const float xv = e ? v1 : v0;
                        const int col = col0 + e;
                        const int cc  = col / 24;
                        const int rem = col - cc * 24;
                        const int hh  = rem / 3;
                        const int ii  = rem - hh * 3;
                        const int bb  = row >> 11;
                        const int nn  = row & 2047;
                        size_t dst;
                        __half* dptr;
                        if (ii == 2) {
                            dptr = g_v;
                            dst = (((size_t)bb * NHEAD + hh) * CHEAD + cc) * SEQ + nn;
                        } else {
                            dptr = (ii == 0) ? g_q : g_k;
                            dst = (((size_t)bb * NHEAD + hh) * SEQ + nn) * CHEAD + cc;
                        }
                        dptr[dst] = __float2half(xv);
                    }
                } else if (EPI == 1) {
                    __half2 o = __floats2half2_rn(fmaxf(v0, 0.f), fmaxf(v1, 0.f));
                    *(__half2*)&((__half*)CoutV)[(size_t)row * N + col0] = o;
                } else {
                    float* Cout = (float*)CoutV;
                    const float2 rr = *(const float2*)&res[(size_t)row * N + col0];
                    float2 o; o.x = v0 + rr.x; o.y = v1 + rr.y;
                    *(float2*)&Cout[(size_t)row * N + col0] = o;
                }
            }
        }
    }
}

// ---------------------------------------- FA2-style fp16 tensor Attention ---
// Q-tile 128/CTA, KV-tile 64. Q pre-scaled by 0.125 at smem load (exact fp16
// exponent shift) -> S natively scaled. l computed from half-rounded P so
// numerator/denominator rounding cancels.
#define AQ_ST 136
#define AV_ST 72
#define ATTN_H   (128*AQ_ST + 64*AQ_ST + 128*AV_ST)
#define ATTN_SMEM_BYTES (ATTN_H*2)   /* 70656 B */

__global__ void __launch_bounds__(256) attn_kernel(const float* __restrict__ x,
                                                   float* __restrict__ out) {
    extern __shared__ __half hsm[];
    __half* sQ  = hsm;                  // [128][136]  (pre-scaled by 0.125)
    __half* sK  = sQ  + 128 * AQ_ST;    // [64][136]
    __half* sVt = sK  + 64  * AQ_ST;    // [128][72]   ([c][kv])

    const int qb = blockIdx.x, h = blockIdx.y, b = blockIdx.z;
    const int tid = threadIdx.x;
    const int wid = tid >> 5, lane = tid & 31;
    const int lq = lane >> 2, lr = lane & 3;

    const uint32_t qB = smem_u32(sQ);
    const uint32_t kB = smem_u32(sK);
    const uint32_t vB = smem_u32(sVt);
    const int aRow = lane & 15, aK = (lane >> 4) * 8;
    const int bRow = (lane & 7) + ((lane >> 4) << 3), bK = ((lane >> 3) & 1) * 8;

    const size_t bh  = ((size_t)b * NHEAD + h) * SEQ;
    const __half* Qg = g_q + (bh + (size_t)qb * 128) * CHEAD;
    const __half* Vb = g_v + ((size_t)b * NHEAD + h) * CHEAD * SEQ;

    const __half2 qscale = __floats2half2_rn(0.125f, 0.125f);
    for (int idx = tid; idx < 128 * 16; idx += 256) {
        const int r = idx >> 4, c8 = (idx & 15) * 8;
        uint4 v = *(const uint4*)&Qg[r * 128 + c8];
        __half2* hv = (__half2*)&v;
        #pragma unroll
        for (int j = 0; j < 4; j++) hv[j] = __hmul2(hv[j], qscale);
        *(uint4*)&sQ[r * AQ_ST + c8] = v;
    }

    float m0 = -1e30f, m1 = -1e30f, l0 = 0.f, l1 = 0.f;
    float oacc[16][4];
    #pragma unroll
    for (int t = 0; t < 16; t++)
        #pragma unroll
        for (int e = 0; e < 4; e++) oacc[t][e] = 0.f;

    for (int kt = 0; kt < SEQ / 64; kt++) {
        __syncthreads();
        const __half* Kg = g_k + (bh + (size_t)kt * 64) * CHEAD;
        for (int idx = tid; idx < 64 * 16; idx += 256) {
            const int r = idx >> 4, c8 = (idx & 15) * 8;
            *(uint4*)&sK[r * AQ_ST + c8] = *(const uint4*)&Kg[r * 128 + c8];
        }
        for (int idx = tid; idx < 128 * 8; idx += 256) {
            const int c = idx >> 3, k8 = (idx & 7) * 8;
            *(uint4*)&sVt[c * AV_ST + k8] =
                *(const uint4*)&Vb[(size_t)c * SEQ + kt * 64 + k8];
        }
        __syncthreads();

        // ---- S = (Q*scale) @ K^T : warp tile 16 x 64 -----------------------
        float sc[8][4];
        #pragma unroll
        for (int g = 0; g < 8; g++)
            #pragma unroll
            for (int e = 0; e < 4; e++) sc[g][e] = 0.f;
        #pragma unroll
        for (int kk = 0; kk < 8; kk++) {
            const int c0 = kk * 16;
            uint32_t a[4], bfr[8][2];
            ldsm4(a, qB + ((wid * 16 + aRow) * AQ_ST + c0 + aK) * 2);
            #pragma unroll
            for (int g4 = 0; g4 < 4; g4++) {
                uint32_t t4[4];
                ldsm4(t4, kB + ((g4 * 16 + bRow) * AQ_ST + c0 + bK) * 2);
                bfr[g4 * 2][0] = t4[0];     bfr[g4 * 2][1] = t4[1];
                bfr[g4 * 2 + 1][0] = t4[2]; bfr[g4 * 2 + 1][1] = t4[3];
            }
            #pragma unroll
            for (int g = 0; g < 8; g++)
                mma16(sc[g], a, bfr[g]);
        }

        // ---- register online softmax (rows lq, lq+8) -----------------------
        float mx0 = -1e30f, mx1 = -1e30f;
        #pragma unroll
        for (int g = 0; g < 8; g++) {
            mx0 = fmaxf(mx0, fmaxf(sc[g][0], sc[g][1]));
            mx1 = fmaxf(mx1, fmaxf(sc[g][2], sc[g][3]));
        }
        mx0 = fmaxf(mx0, __shfl_xor_sync(0xffffffffu, mx0, 1));
        mx0 = fmaxf(mx0, __shfl_xor_sync(0xffffffffu, mx0, 2));
        mx1 = fmaxf(mx1, __shfl_xor_sync(0xffffffffu, mx1, 1));
        mx1 = fmaxf(mx1, __shfl_xor_sync(0xffffffffu, mx1, 2));
        const float mn0 = fmaxf(m0, mx0), mn1 = fmaxf(m1, mx1);
        const float al0 = __expf(m0 - mn0), al1 = __expf(m1 - mn1);
        m0 = mn0; m1 = mn1;

        uint32_t aP[4][4];
        float sum0 = 0.f, sum1 = 0.f;
        #pragma unroll
        for (int g = 0; g < 8; g++) {
            const float p0 = __expf(sc[g][0] - mn0);
            const float p1 = __expf(sc[g][1] - mn0);
            const float p2 = __expf(sc[g][2] - mn1);
            const float p3 = __expf(sc[g][3] - mn1);
            const __half2 ph01 = __floats2half2_rn(p0, p1);
            const __half2 ph23 = __floats2half2_rn(p2, p3);
            const float2 f01 = __half22float2(ph01);
            const float2 f23 = __half22float2(ph23);
            sum0 += f01.x + f01.y;
            sum1 += f23.x + f23.y;
            const int kk = g >> 1, hi = (g & 1) * 2;
            aP[kk][hi]     = h2u(ph01);
            aP[kk][hi + 1] = h2u(ph23);
        }
        sum0 += __shfl_xor_sync(0xffffffffu, sum0, 1);
        sum0 += __shfl_xor_sync(0xffffffffu, sum0, 2);
        sum1 += __shfl_xor_sync(0xffffffffu, sum1, 1);
        sum1 += __shfl_xor_sync(0xffffffffu, sum1, 2);
        l0 = l0 * al0 + sum0;
        l1 = l1 * al1 + sum1;

        // ---- O = O*alpha + P @ V : warp tile 16 x 128 -----------------------
        #pragma unroll
        for (int t = 0; t < 16; t++) {
            oacc[t][0] *= al0; oacc[t][1] *= al0;
            oacc[t][2] *= al1; oacc[t][3] *= al1;
        }
        #pragma unroll
        for (int kk = 0; kk < 4; kk++) {
            const int c0 = kk * 16;
            uint32_t bfr[16][2];
            #pragma unroll
            for (int f4 = 0; f4 < 8; f4++) {
                uint32_t t4[4];
                ldsm4(t4, vB + ((f4 * 16 + bRow) * AV_ST + c0 + bK) * 2);
                bfr[f4 * 2][0] = t4[0];     bfr[f4 * 2][1] = t4[1];
                bfr[f4 * 2 + 1][0] = t4[2]; bfr[f4 * 2 + 1][1] = t4[3];
            }
            #pragma unroll
            for (int t = 0; t < 16; t++)
                mma16(oacc[t], aP[kk], bfr[t]);
        }
    }

    // ------------------------------ epilogue --------------------------------
    const float inv0 = 1.f / l0, inv1 = 1.f / l1;
    const int q0 = qb * 128 + wid * 16 + lq;
    #pragma unroll
    for (int t = 0; t < 16; t++) {
        const int col = t * 8 + lr * 2;
        const size_t b0 = ((size_t)b * SEQ + q0) * D_MODEL + h * CHEAD + col;
        const size_t b1 = ((size_t)b * SEQ + q0 + 8) * D_MODEL + h * CHEAD + col;
        const float2 x0 = *(const float2*)&x[b0];
        const float2 x1 = *(const float2*)&x[b1];
        float2 o0, o1;
        o0.x = oacc[t][0] * inv0 + x0.x; o0.y = oacc[t][1] * inv0 + x0.y;
        o1.x = oacc[t][2] * inv1 + x1.x; o1.y = oacc[t][3] * inv1 + x1.y;
        *(float2*)&out[b0] = o0;
        *(float2*)&out[b1] = o1;
    }
}

// ------------------------------------------------------------------ launch --
extern "C" void kernel_launch(void* const* d_in, const int* in_sizes, int n_in,
                              void* d_out, int out_size) {
    const float* x    = (const float*)d_in[0];
    const float* ln_g = (const float*)d_in[1];
    const float* ln_b = (const float*)d_in[2];
    const float* w3   = (const float*)d_in[3];
    const float* b3   = (const float*)d_in[4];
    const float* w1   = (const float*)d_in[5];
    const float* b1   = (const float*)d_in[6];
    const float* w2   = (const float*)d_in[7];
    const float* b2   = (const float*)d_in[8];
    float* out = (float*)d_out;

    __half *yh, *h1, *wh;
    float *att;
    cudaGetSymbolAddress((void**)&yh,  g_yh);
    cudaGetSymbolAddress((void**)&att, g_att);
    cudaGetSymbolAddress((void**)&h1,  g_h1);
    cudaGetSymbolAddress((void**)&wh,  g_wh);

    cudaFuncSetAttribute(attn_kernel, cudaFuncAttributeMaxDynamicSharedMemorySize,
                         ATTN_SMEM_BYTES);
    cudaFuncSetAttribute(mgemm_kernel<0>, cudaFuncAttributeMaxDynamicSharedMemorySize,
                         GEMM_SMEM_BYTES);
    cudaFuncSetAttribute(mgemm_kernel<1>, cudaFuncAttributeMaxDynamicSharedMemorySize,
                         GEMM_SMEM_BYTES);
    cudaFuncSetAttribute(mgemm_kernel<2>, cudaFuncAttributeMaxDynamicSharedMemorySize,
                         GEMM_SMEM_BYTES);

    tc_kernel<<<dim3(3072/32, 1024/32), dim3(32, 8)>>>(w3, wh + WH3_OFF, 1024, 3072);
    tc_kernel<<<dim3(4096/32, 1024/32), dim3(32, 8)>>>(w1, wh + WH1_OFF, 1024, 4096);
    tc_kernel<<<dim3(1024/32, 4096/32), dim3(32, 8)>>>(w2, wh + WH2_OFF, 4096, 1024);

    ln_kernel<<<ROWS, 256>>>(x, ln_g, ln_b, yh);
    mgemm_kernel<0><<<dim3(3072/128, ROWS/128), 256, GEMM_SMEM_BYTES>>>(
        yh, wh + WH3_OFF, b3, nullptr, nullptr, ROWS, 3072, 1024);
    attn_kernel<<<dim3(SEQ/128, NHEAD, BATCH), 256, ATTN_SMEM_BYTES>>>(x, att);
    ln_kernel<<<ROWS, 256>>>(att, ln_g, ln_b, yh);
    mgemm_kernel<1><<<dim3(4096/128, ROWS/128), 256, GEMM_SMEM_BYTES>>>(
        yh, wh + WH1_OFF, b1, nullptr, h1, ROWS, 4096, 1024);
    mgemm_kernel<2><<<dim3(1024/128, ROWS/128), 256, GEMM_SMEM_BYTES>>>(
        h1, wh + WH2_OFF, b2, att, out, ROWS, 1024, 4096);
}

// round 13
// speedup vs baseline: 1.5038x; 1.1494x over previous
#include <cuda_runtime.h>
#include <cuda_fp16.h>
#include <math.h>
#include <stdint.h>

#define D_MODEL 1024
#define NHEAD 8
#define CHEAD 128
#define BATCH 4
#define SEQ 2048
#define ROWS (BATCH*SEQ)   /* 8192 */

// ---------------- scratch (module-static device memory; no runtime allocs) ---
__device__ __align__(128) __half g_yh [ROWS * D_MODEL];
__device__ __align__(128) __half g_q  [BATCH * NHEAD * SEQ * CHEAD]; // [b][h][n][c]
__device__ __align__(128) __half g_k  [BATCH * NHEAD * SEQ * CHEAD]; // [b][h][n][c]
__device__ __align__(128) __half g_v  [BATCH * NHEAD * CHEAD * SEQ]; // [b][h][c][n]
__device__ __align__(128) float  g_att[ROWS * D_MODEL];
__device__ __align__(128) __half g_h1 [ROWS * 4 * D_MODEL];
__device__ __align__(128) float  g_b3p[3 * D_MODEL];                 // permuted b3
#define WH3_OFF 0
#define WH1_OFF (3072*1024)
#define WH2_OFF (WH1_OFF + 4096*1024)
__device__ __align__(128) __half g_wh [WH2_OFF + 1024*4096];

// ------------------------------------------------------------ PTX helpers ---
__device__ __forceinline__ uint32_t smem_u32(const void* p) {
    uint32_t r;
    asm("{ .reg .u64 t; cvta.to.shared.u64 t, %1; cvt.u32.u64 %0, t; }"
        : "=r"(r) : "l"(p));
    return r;
}
__device__ __forceinline__ void cp16(uint32_t dst, const void* src) {
    asm volatile("cp.async.ca.shared.global [%0], [%1], 16;\n" :: "r"(dst), "l"(src));
}
__device__ __forceinline__ void cp_commit() {
    asm volatile("cp.async.commit_group;\n" ::: "memory");
}
__device__ __forceinline__ void cp_wait1() {
    asm volatile("cp.async.wait_group 1;\n" ::: "memory");
}
__device__ __forceinline__ void ldsm4(uint32_t* r, uint32_t addr) {
    asm volatile("ldmatrix.sync.aligned.m8n8.x4.shared.b16 {%0,%1,%2,%3}, [%4];"
        : "=r"(r[0]), "=r"(r[1]), "=r"(r[2]), "=r"(r[3]) : "r"(addr));
}
__device__ __forceinline__ void mma16(float* c, const uint32_t* a, const uint32_t* b) {
    asm volatile(
        "mma.sync.aligned.m16n8k16.row.col.f32.f16.f16.f32 "
        "{%0,%1,%2,%3}, {%4,%5,%6,%7}, {%8,%9}, {%0,%1,%2,%3};"
        : "+f"(c[0]), "+f"(c[1]), "+f"(c[2]), "+f"(c[3])
        : "r"(a[0]), "r"(a[1]), "r"(a[2]), "r"(a[3]), "r"(b[0]), "r"(b[1]));
}
__device__ __forceinline__ uint32_t h2u(__half2 h) {
    return *(uint32_t*)&h;
}

// ------------------------------------------- weight transpose+convert -------
__global__ void __launch_bounds__(256) tc_kernel(const float* __restrict__ in,
                                                 __half* __restrict__ out,
                                                 int K, int N) {
    __shared__ float t[32][33];
    const int nb = blockIdx.x * 32, kb = blockIdx.y * 32;
    const int tx = threadIdx.x, ty = threadIdx.y;
    #pragma unroll
    for (int i = 0; i < 32; i += 8)
        t[ty + i][tx] = in[(size_t)(kb + ty + i) * N + nb + tx];
    __syncthreads();
    #pragma unroll
    for (int i = 0; i < 32; i += 8)
        out[(size_t)(nb + ty + i) * K + kb + tx] = __float2half(t[tx][ty + i]);
}

// w3 variant: output ROW index permuted  n=(c*24+h*3+i) -> n'=i*1024+h*128+c
__global__ void __launch_bounds__(256) tc_qkv_kernel(const float* __restrict__ in,
                                                     __half* __restrict__ out,
                                                     int K, int N) {
    __shared__ float t[32][33];
    const int nb = blockIdx.x * 32, kb = blockIdx.y * 32;
    const int tx = threadIdx.x, ty = threadIdx.y;
    #pragma unroll
    for (int i = 0; i < 32; i += 8)
        t[ty + i][tx] = in[(size_t)(kb + ty + i) * N + nb + tx];
    __syncthreads();
    #pragma unroll
    for (int i = 0; i < 32; i += 8) {
        const int n  = nb + ty + i;
        const int c  = n / 24;
        const int rm = n - c * 24;
        const int hh = rm / 3;
        const int ii = rm - hh * 3;
        const size_t np = (size_t)ii * 1024 + hh * 128 + c;
        out[np * K + kb + tx] = __float2half(t[tx][ty + i]);
    }
}

__global__ void __launch_bounds__(256) permb_kernel(const float* __restrict__ in,
                                                    float* __restrict__ out) {
    const int n = blockIdx.x * 256 + threadIdx.x;
    if (n < 3 * D_MODEL) {
        const int c  = n / 24;
        const int rm = n - c * 24;
        const int hh = rm / 3;
        const int ii = rm - hh * 3;
        out[ii * 1024 + hh * 128 + c] = in[n];
    }
}

// ---------------------------------------------------------------- LayerNorm --
// 256 threads, 4 floats per thread (float4), half outputs packed as uint2.
__global__ void __launch_bounds__(256) ln_kernel(const float* __restrict__ in,
                                                 const float* __restrict__ gamma,
                                                 const float* __restrict__ beta,
                                                 __half* __restrict__ out) {
    const int row = blockIdx.x;
    const int tid = threadIdx.x;
    const float4 v = ((const float4*)(in + (size_t)row * D_MODEL))[tid];
    float s  = v.x + v.y + v.z + v.w;
    float sq = v.x * v.x + v.y * v.y + v.z * v.z + v.w * v.w;
    #pragma unroll
    for (int o = 16; o; o >>= 1) {
        s  += __shfl_xor_sync(0xffffffffu, s,  o);
        sq += __shfl_xor_sync(0xffffffffu, sq, o);
    }
    __shared__ float ws[8], wq[8];
    const int w = tid >> 5, l = tid & 31;
    if (l == 0) { ws[w] = s; wq[w] = sq; }
    __syncthreads();
    if (tid == 0) {
        float ts = 0.f, tq = 0.f;
        #pragma unroll
        for (int i = 0; i < 8; i++) { ts += ws[i]; tq += wq[i]; }
        ws[0] = ts; wq[0] = tq;
    }
    __syncthreads();
    const float mu  = ws[0] * (1.f / D_MODEL);
    const float var = wq[0] * (1.f / D_MODEL) - mu * mu;
    const float rs  = rsqrtf(var + 1e-3f);
    const float4 g  = ((const float4*)gamma)[tid];
    const float4 be = ((const float4*)beta)[tid];
    const __half2 h01 = __floats2half2_rn((v.x - mu) * rs * g.x + be.x,
                                          (v.y - mu) * rs * g.y + be.y);
    const __half2 h23 = __floats2half2_rn((v.z - mu) * rs * g.z + be.z,
                                          (v.w - mu) * rs * g.w + be.w);
    uint2 o; o.x = h2u(h01); o.y = h2u(h23);
    ((uint2*)(out + (size_t)row * D_MODEL))[tid] = o;
}

// ------------------------------------------------ FP16 mma.sync GEMM --------
// CTA 128x128, BK=64, 8 warps (2x4), warp tile 64x32, 3-stage cp.async.
#define GST 72
#define GS_HALVES (128*GST)
#define GEMM_SMEM_BYTES (6*GS_HALVES*2)   /* 110592 B */

__device__ __forceinline__ void g_load_stage(const __half* __restrict__ Ag,
                                             const __half* __restrict__ Bg,
                                             int K, uint32_t aBase, uint32_t bBase,
                                             int k0, int tid) {
    #pragma unroll
    for (int p = 0; p < 4; p++) {
        const int id = p * 256 + tid;
        const int r = id >> 3, c8 = (id & 7) * 8;
        cp16(aBase + (r * GST + c8) * 2, Ag + (size_t)r * K + k0 + c8);
        cp16(bBase + (r * GST + c8) * 2, Bg + (size_t)r * K + k0 + c8);
    }
    cp_commit();
}

// EPI 0: bias+relu, QKV store (permuted cols: [i][h][c]) ;
// EPI 1: bias+relu->half ; EPI 2: bias+residual->f32
template<int EPI>
__global__ void __launch_bounds__(256, 2) mgemm_kernel(const __half* __restrict__ A,
                                                       const __half* __restrict__ WT,
                                                       const float* __restrict__ bias,
                                                       const float* __restrict__ res,
                                                       void* __restrict__ CoutV,
                                                       int M, int N, int K) {
    extern __shared__ __half hsm[];

    const int tid = threadIdx.x;
    const int wid = tid >> 5, lane = tid & 31;
    const int wm = wid & 1, wn = wid >> 1;
    const int lq = lane >> 2, lr = lane & 3;
    const int bx = blockIdx.x, by = blockIdx.y;

    const __half* Ag = A  + (size_t)(by * 128) * K;
    const __half* Bg = WT + (size_t)(bx * 128) * K;

    uint32_t aBase[3], bBase[3];
    #pragma unroll
    for (int s = 0; s < 3; s++) {
        aBase[s] = smem_u32(hsm + (2 * s)     * GS_HALVES);
        bBase[s] = smem_u32(hsm + (2 * s + 1) * GS_HALVES);
    }

    const int aRow = lane & 15, aK = (lane >> 4) * 8;
    const int bRow = (lane & 7) + ((lane >> 4) << 3), bK = ((lane >> 3) & 1) * 8;

    float acc[4][4][4];
    #pragma unroll
    for (int f = 0; f < 4; f++)
        #pragma unroll
        for (int g = 0; g < 4; g++)
            #pragma unroll
            for (int e = 0; e < 4; e++) acc[f][g][e] = 0.f;

    const int iters = K >> 6;
    g_load_stage(Ag, Bg, K, aBase[0], bBase[0], 0, tid);
    g_load_stage(Ag, Bg, K, aBase[1], bBase[1], 64, tid);

    int s = 0;
    for (int it = 0; it < iters; it++) {
        cp_wait1();
        __syncthreads();
        if (it + 2 < iters) {
            int ns = s + 2; if (ns >= 3) ns -= 3;
            g_load_stage(Ag, Bg, K, aBase[ns], bBase[ns], (it + 2) << 6, tid);
        }

        #pragma unroll
        for (int kk = 0; kk < 4; kk++) {
            const int c0 = kk * 16;
            uint32_t a[4][4], b[4][2];
            #pragma unroll
            for (int f = 0; f < 4; f++)
                ldsm4(a[f], aBase[s] + ((wm * 64 + f * 16 + aRow) * GST + c0 + aK) * 2);
            #pragma unroll
            for (int g2 = 0; g2 < 2; g2++) {
                uint32_t t4[4];
                ldsm4(t4, bBase[s] + ((wn * 32 + g2 * 16 + bRow) * GST + c0 + bK) * 2);
                b[g2 * 2][0] = t4[0];     b[g2 * 2][1] = t4[1];
                b[g2 * 2 + 1][0] = t4[2]; b[g2 * 2 + 1][1] = t4[3];
            }
            #pragma unroll
            for (int f = 0; f < 4; f++)
                #pragma unroll
                for (int g = 0; g < 4; g++)
                    mma16(acc[f][g], a[f], b[g]);
        }
        s = (s == 2) ? 0 : s + 1;
    }

    #pragma unroll
    for (int f = 0; f < 4; f++) {
        #pragma unroll
        for (int g = 0; g < 4; g++) {
            const int row0 = by * 128 + wm * 64 + f * 16 + lq;
            const int col0 = bx * 128 + wn * 32 + g * 8 + lr * 2;
            #pragma unroll
            for (int h = 0; h < 2; h++) {
                const int row = row0 + h * 8;
                float v0 = acc[f][g][h * 2 + 0] + bias[col0];
                float v1 = acc[f][g][h * 2 + 1] + bias[col0 + 1];
                if (EPI == 0) {
                    v0 = fmaxf(v0, 0.f); v1 = fmaxf(v1, 0.f);
                    // permuted col: col0 = i*1024 + h*128 + c
                    const int reg = col0 >> 10;          // 0=q 1=k 2=v
                    const int hh  = (col0 >> 7) & 7;
                    const int cc  = col0 & 127;
                    const int bb  = row >> 11;
                    const int nn  = row & 2047;
                    if (reg == 2) {
                        const size_t base =
                            (((size_t)bb * NHEAD + hh) * CHEAD + cc) * SEQ + nn;
                        g_v[base]       = __float2half(v0);
                        g_v[base + SEQ] = __float2half(v1);
                    } else {
                        __half* dptr = reg ? g_k : g_q;
                        const size_t base =
                            (((size_t)bb * NHEAD + hh) * SEQ + nn) * CHEAD + cc;
                        *(__half2*)&dptr[base] = __floats2half2_rn(v0, v1);
                    }
                } else if (EPI == 1) {
                    __half2 o = __floats2half2_rn(fmaxf(v0, 0.f), fmaxf(v1, 0.f));
                    *(__half2*)&((__half*)CoutV)[(size_t)row * N + col0] = o;
                } else {
                    float* Cout = (float*)CoutV;
                    const float2 rr = *(const float2*)&res[(size_t)row * N + col0];
                    float2 o; o.x = v0 + rr.x; o.y = v1 + rr.y;
                    *(float2*)&Cout[(size_t)row * N + col0] = o;
                }
            }
        }
    }
}

// ---------------------------------------- FA2-style fp16 tensor Attention ---
#define AQ_ST 136
#define AV_ST 72
#define ATTN_H   (128*AQ_ST + 64*AQ_ST + 128*AV_ST)
#define ATTN_SMEM_BYTES (ATTN_H*2)   /* 70656 B */

__global__ void __launch_bounds__(256) attn_kernel(const float* __restrict__ x,
                                                   float* __restrict__ out) {
    extern __shared__ __half hsm[];
    __half* sQ  = hsm;                  // [128][136]  (pre-scaled by 0.125)
    __half* sK  = sQ  + 128 * AQ_ST;    // [64][136]
    __half* sVt = sK  + 64  * AQ_ST;    // [128][72]   ([c][kv])

    const int qb = blockIdx.x, h = blockIdx.y, b = blockIdx.z;
    const int tid = threadIdx.x;
    const int wid = tid >> 5, lane = tid & 31;
    const int lq = lane >> 2, lr = lane & 3;

    const uint32_t qB = smem_u32(sQ);
    const uint32_t kB = smem_u32(sK);
    const uint32_t vB = smem_u32(sVt);
    const int aRow = lane & 15, aK = (lane >> 4) * 8;
    const int bRow = (lane & 7) + ((lane >> 4) << 3), bK = ((lane >> 3) & 1) * 8;

    const size_t bh  = ((size_t)b * NHEAD + h) * SEQ;
    const __half* Qg = g_q + (bh + (size_t)qb * 128) * CHEAD;
    const __half* Vb = g_v + ((size_t)b * NHEAD + h) * CHEAD * SEQ;

    const __half2 qscale = __floats2half2_rn(0.125f, 0.125f);
    for (int idx = tid; idx < 128 * 16; idx += 256) {
        const int r = idx >> 4, c8 = (idx & 15) * 8;
        uint4 v = *(const uint4*)&Qg[r * 128 + c8];
        __half2* hv = (__half2*)&v;
        #pragma unroll
        for (int j = 0; j < 4; j++) hv[j] = __hmul2(hv[j], qscale);
        *(uint4*)&sQ[r * AQ_ST + c8] = v;
    }

    float m0 = -1e30f, m1 = -1e30f, l0 = 0.f, l1 = 0.f;
    float oacc[16][4];
    #pragma unroll
    for (int t = 0; t < 16; t++)
        #pragma unroll
        for (int e = 0; e < 4; e++) oacc[t][e] = 0.f;

    for (int kt = 0; kt < SEQ / 64; kt++) {
        __syncthreads();
        const __half* Kg = g_k + (bh + (size_t)kt * 64) * CHEAD;
        for (int idx = tid; idx < 64 * 16; idx += 256) {
            const int r = idx >> 4, c8 = (idx & 15) * 8;
            *(uint4*)&sK[r * AQ_ST + c8] = *(const uint4*)&Kg[r * 128 + c8];
        }
        for (int idx = tid; idx < 128 * 8; idx += 256) {
            const int c = idx >> 3, k8 = (idx & 7) * 8;
            *(uint4*)&sVt[c * AV_ST + k8] =
                *(const uint4*)&Vb[(size_t)c * SEQ + kt * 64 + k8];
        }
        __syncthreads();

        // ---- S = (Q*scale) @ K^T -------------------------------------------
        float sc[8][4];
        #pragma unroll
        for (int g = 0; g < 8; g++)
            #pragma unroll
            for (int e = 0; e < 4; e++) sc[g][e] = 0.f;
        #pragma unroll
        for (int kk = 0; kk < 8; kk++) {
            const int c0 = kk * 16;
            uint32_t a[4], bfr[8][2];
            ldsm4(a, qB + ((wid * 16 + aRow) * AQ_ST + c0 + aK) * 2);
            #pragma unroll
            for (int g4 = 0; g4 < 4; g4++) {
                uint32_t t4[4];
                ldsm4(t4, kB + ((g4 * 16 + bRow) * AQ_ST + c0 + bK) * 2);
                bfr[g4 * 2][0] = t4[0];     bfr[g4 * 2][1] = t4[1];
                bfr[g4 * 2 + 1][0] = t4[2]; bfr[g4 * 2 + 1][1] = t4[3];
            }
            #pragma unroll
            for (int g = 0; g < 8; g++)
                mma16(sc[g], a, bfr[g]);
        }

        // ---- register online softmax ----------------------------------------
        float mx0 = -1e30f, mx1 = -1e30f;
        #pragma unroll
        for (int g = 0; g < 8; g++) {
            mx0 = fmaxf(mx0, fmaxf(sc[g][0], sc[g][1]));
            mx1 = fmaxf(mx1, fmaxf(sc[g][2], sc[g][3]));
        }
        mx0 = fmaxf(mx0, __shfl_xor_sync(0xffffffffu, mx0, 1));
        mx0 = fmaxf(mx0, __shfl_xor_sync(0xffffffffu, mx0, 2));
        mx1 = fmaxf(mx1, __shfl_xor_sync(0xffffffffu, mx1, 1));
        mx1 = fmaxf(mx1, __shfl_xor_sync(0xffffffffu, mx1, 2));
        const float mn0 = fmaxf(m0, mx0), mn1 = fmaxf(m1, mx1);
        const float al0 = __expf(m0 - mn0), al1 = __expf(m1 - mn1);
        m0 = mn0; m1 = mn1;

        uint32_t aP[4][4];
        float sum0 = 0.f, sum1 = 0.f;
        #pragma unroll
        for (int g = 0; g < 8; g++) {
            const float p0 = __expf(sc[g][0] - mn0);
            const float p1 = __expf(sc[g][1] - mn0);
            const float p2 = __expf(sc[g][2] - mn1);
            const float p3 = __expf(sc[g][3] - mn1);
            const __half2 ph01 = __floats2half2_rn(p0, p1);
            const __half2 ph23 = __floats2half2_rn(p2, p3);
            const float2 f01 = __half22float2(ph01);
            const float2 f23 = __half22float2(ph23);
            sum0 += f01.x + f01.y;
            sum1 += f23.x + f23.y;
            const int kk = g >> 1, hi = (g & 1) * 2;
            aP[kk][hi]     = h2u(ph01);
            aP[kk][hi + 1] = h2u(ph23);
        }
        sum0 += __shfl_xor_sync(0xffffffffu, sum0, 1);
        sum0 += __shfl_xor_sync(0xffffffffu, sum0, 2);
        sum1 += __shfl_xor_sync(0xffffffffu, sum1, 1);
        sum1 += __shfl_xor_sync(0xffffffffu, sum1, 2);
        l0 = l0 * al0 + sum0;
        l1 = l1 * al1 + sum1;

        // ---- O = O*alpha + P @ V --------------------------------------------
        #pragma unroll
        for (int t = 0; t < 16; t++) {
            oacc[t][0] *= al0; oacc[t][1] *= al0;
            oacc[t][2] *= al1; oacc[t][3] *= al1;
        }
        #pragma unroll
        for (int kk = 0; kk < 4; kk++) {
            const int c0 = kk * 16;
            uint32_t bfr[16][2];
            #pragma unroll
            for (int f4 = 0; f4 < 8; f4++) {
                uint32_t t4[4];
                ldsm4(t4, vB + ((f4 * 16 + bRow) * AV_ST + c0 + bK) * 2);
                bfr[f4 * 2][0] = t4[0];     bfr[f4 * 2][1] = t4[1];
                bfr[f4 * 2 + 1][0] = t4[2]; bfr[f4 * 2 + 1][1] = t4[3];
            }
            #pragma unroll
            for (int t = 0; t < 16; t++)
                mma16(oacc[t], aP[kk], bfr[t]);
        }
    }

    // ------------------------------ epilogue --------------------------------
    const float inv0 = 1.f / l0, inv1 = 1.f / l1;
    const int q0 = qb * 128 + wid * 16 + lq;
    #pragma unroll
    for (int t = 0; t < 16; t++) {
        const int col = t * 8 + lr * 2;
        const size_t b0 = ((size_t)b * SEQ + q0) * D_MODEL + h * CHEAD + col;
        const size_t b1 = ((size_t)b * SEQ + q0 + 8) * D_MODEL + h * CHEAD + col;
        const float2 x0 = *(const float2*)&x[b0];
        const float2 x1 = *(const float2*)&x[b1];
        float2 o0, o1;
        o0.x = oacc[t][0] * inv0 + x0.x; o0.y = oacc[t][1] * inv0 + x0.y;
        o1.x = oacc[t][2] * inv1 + x1.x; o1.y = oacc[t][3] * inv1 + x1.y;
        *(float2*)&out[b0] = o0;
        *(float2*)&out[b1] = o1;
    }
}

// ------------------------------------------------------------------ launch --
extern "C" void kernel_launch(void* const* d_in, const int* in_sizes, int n_in,
                              void* d_out, int out_size) {
    const float* x    = (const float*)d_in[0];
    const float* ln_g = (const float*)d_in[1];
    const float* ln_b = (const float*)d_in[2];
    const float* w3   = (const float*)d_in[3];
    const float* b3   = (const float*)d_in[4];
    const float* w1   = (const float*)d_in[5];
    const float* b1   = (const float*)d_in[6];
    const float* w2   = (const float*)d_in[7];
    const float* b2   = (const float*)d_in[8];
    float* out = (float*)d_out;

    __half *yh, *h1, *wh;
    float *att, *b3p;
    cudaGetSymbolAddress((void**)&yh,  g_yh);
    cudaGetSymbolAddress((void**)&att, g_att);
    cudaGetSymbolAddress((void**)&h1,  g_h1);
    cudaGetSymbolAddress((void**)&wh,  g_wh);
    cudaGetSymbolAddress((void**)&b3p, g_b3p);

    cudaFuncSetAttribute(attn_kernel, cudaFuncAttributeMaxDynamicSharedMemorySize,
                         ATTN_SMEM_BYTES);
    cudaFuncSetAttribute(mgemm_kernel<0>, cudaFuncAttributeMaxDynamicSharedMemorySize,
                         GEMM_SMEM_BYTES);
    cudaFuncSetAttribute(mgemm_kernel<1>, cudaFuncAttributeMaxDynamicSharedMemorySize,
                         GEMM_SMEM_BYTES);
    cudaFuncSetAttribute(mgemm_kernel<2>, cudaFuncAttributeMaxDynamicSharedMemorySize,
                         GEMM_SMEM_BYTES);

    tc_qkv_kernel<<<dim3(3072/32, 1024/32), dim3(32, 8)>>>(w3, wh + WH3_OFF, 1024, 3072);
    tc_kernel<<<dim3(4096/32, 1024/32), dim3(32, 8)>>>(w1, wh + WH1_OFF, 1024, 4096);
    tc_kernel<<<dim3(1024/32, 4096/32), dim3(32, 8)>>>(w2, wh + WH2_OFF, 4096, 1024);
    permb_kernel<<<12, 256>>>(b3, b3p);

    ln_kernel<<<ROWS, 256>>>(x, ln_g, ln_b, yh);
    mgemm_kernel<0><<<dim3(3072/128, ROWS/128), 256, GEMM_SMEM_BYTES>>>(
        yh, wh + WH3_OFF, b3p, nullptr, nullptr, ROWS, 3072, 1024);
    attn_kernel<<<dim3(SEQ/128, NHEAD, BATCH), 256, ATTN_SMEM_BYTES>>>(x, att);
    ln_kernel<<<ROWS, 256>>>(att, ln_g, ln_b, yh);
    mgemm_kernel<1><<<dim3(4096/128, ROWS/128), 256, GEMM_SMEM_BYTES>>>(
        yh, wh + WH1_OFF, b1, nullptr, h1, ROWS, 4096, 1024);
    mgemm_kernel<2><<<dim3(1024/128, ROWS/128), 256, GEMM_SMEM_BYTES>>>(
        h1, wh + WH2_OFF, b2, att, out, ROWS, 1024, 4096);
}

// round 14
// speedup vs baseline: 1.5523x; 1.0322x over previous
#include <cuda_runtime.h>
#include <cuda_fp16.h>
#include <math.h>
#include <stdint.h>

#define D_MODEL 1024
#define NHEAD 8
#define CHEAD 128
#define BATCH 4
#define SEQ 2048
#define ROWS (BATCH*SEQ)   /* 8192 */

// ---------------- scratch (module-static device memory; no runtime allocs) ---
__device__ __align__(128) __half g_yh [ROWS * D_MODEL];
__device__ __align__(128) __half g_q  [BATCH * NHEAD * SEQ * CHEAD]; // [b][h][n][c]
__device__ __align__(128) __half g_k  [BATCH * NHEAD * SEQ * CHEAD]; // [b][h][n][c]
__device__ __align__(128) __half g_v  [BATCH * NHEAD * CHEAD * SEQ]; // [b][h][c][n]
__device__ __align__(128) float  g_att[ROWS * D_MODEL];
__device__ __align__(128) __half g_h1 [ROWS * 4 * D_MODEL];
__device__ __align__(128) float  g_b3p[3 * D_MODEL];                 // permuted b3
#define WH3_OFF 0
#define WH1_OFF (3072*1024)
#define WH2_OFF (WH1_OFF + 4096*1024)
__device__ __align__(128) __half g_wh [WH2_OFF + 1024*4096];

// ------------------------------------------------------------ PTX helpers ---
__device__ __forceinline__ uint32_t smem_u32(const void* p) {
    uint32_t r;
    asm("{ .reg .u64 t; cvta.to.shared.u64 t, %1; cvt.u32.u64 %0, t; }"
        : "=r"(r) : "l"(p));
    return r;
}
__device__ __forceinline__ void cp16(uint32_t dst, const void* src) {
    asm volatile("cp.async.ca.shared.global [%0], [%1], 16;\n" :: "r"(dst), "l"(src));
}
__device__ __forceinline__ void cp_commit() {
    asm volatile("cp.async.commit_group;\n" ::: "memory");
}
__device__ __forceinline__ void cp_wait1() {
    asm volatile("cp.async.wait_group 1;\n" ::: "memory");
}
__device__ __forceinline__ void ldsm4(uint32_t* r, uint32_t addr) {
    asm volatile("ldmatrix.sync.aligned.m8n8.x4.shared.b16 {%0,%1,%2,%3}, [%4];"
        : "=r"(r[0]), "=r"(r[1]), "=r"(r[2]), "=r"(r[3]) : "r"(addr));
}
__device__ __forceinline__ void mma16(float* c, const uint32_t* a, const uint32_t* b) {
    asm volatile(
        "mma.sync.aligned.m16n8k16.row.col.f32.f16.f16.f32 "
        "{%0,%1,%2,%3}, {%4,%5,%6,%7}, {%8,%9}, {%0,%1,%2,%3};"
        : "+f"(c[0]), "+f"(c[1]), "+f"(c[2]), "+f"(c[3])
        : "r"(a[0]), "r"(a[1]), "r"(a[2]), "r"(a[3]), "r"(b[0]), "r"(b[1]));
}
__device__ __forceinline__ uint32_t h2u(__half2 h) {
    return *(uint32_t*)&h;
}

// ------------------------------------------- weight transpose+convert -------
__global__ void __launch_bounds__(256) tc_kernel(const float* __restrict__ in,
                                                 __half* __restrict__ out,
                                                 int K, int N) {
    __shared__ float t[32][33];
    const int nb = blockIdx.x * 32, kb = blockIdx.y * 32;
    const int tx = threadIdx.x, ty = threadIdx.y;
    #pragma unroll
    for (int i = 0; i < 32; i += 8)
        t[ty + i][tx] = in[(size_t)(kb + ty + i) * N + nb + tx];
    __syncthreads();
    #pragma unroll
    for (int i = 0; i < 32; i += 8)
        out[(size_t)(nb + ty + i) * K + kb + tx] = __float2half(t[tx][ty + i]);
}

// w3 variant: output ROW index permuted  n=(c*24+h*3+i) -> n'=i*1024+h*128+c
__global__ void __launch_bounds__(256) tc_qkv_kernel(const float* __restrict__ in,
                                                     __half* __restrict__ out,
                                                     int K, int N) {
    __shared__ float t[32][33];
    const int nb = blockIdx.x * 32, kb = blockIdx.y * 32;
    const int tx = threadIdx.x, ty = threadIdx.y;
    #pragma unroll
    for (int i = 0; i < 32; i += 8)
        t[ty + i][tx] = in[(size_t)(kb + ty + i) * N + nb + tx];
    __syncthreads();
    #pragma unroll
    for (int i = 0; i < 32; i += 8) {
        const int n  = nb + ty + i;
        const int c  = n / 24;
        const int rm = n - c * 24;
        const int hh = rm / 3;
        const int ii = rm - hh * 3;
        const size_t np = (size_t)ii * 1024 + hh * 128 + c;
        out[np * K + kb + tx] = __float2half(t[tx][ty + i]);
    }
}

__global__ void __launch_bounds__(256) permb_kernel(const float* __restrict__ in,
                                                    float* __restrict__ out) {
    const int n = blockIdx.x * 256 + threadIdx.x;
    if (n < 3 * D_MODEL) {
        const int c  = n / 24;
        const int rm = n - c * 24;
        const int hh = rm / 3;
        const int ii = rm - hh * 3;
        out[ii * 1024 + hh * 128 + c] = in[n];
    }
}

// ---------------------------------------------------------------- LayerNorm --
__global__ void __launch_bounds__(256) ln_kernel(const float* __restrict__ in,
                                                 const float* __restrict__ gamma,
                                                 const float* __restrict__ beta,
                                                 __half* __restrict__ out) {
    const int row = blockIdx.x;
    const int tid = threadIdx.x;
    const float4 v = ((const float4*)(in + (size_t)row * D_MODEL))[tid];
    float s  = v.x + v.y + v.z + v.w;
    float sq = v.x * v.x + v.y * v.y + v.z * v.z + v.w * v.w;
    #pragma unroll
    for (int o = 16; o; o >>= 1) {
        s  += __shfl_xor_sync(0xffffffffu, s,  o);
        sq += __shfl_xor_sync(0xffffffffu, sq, o);
    }
    __shared__ float ws[8], wq[8];
    const int w = tid >> 5, l = tid & 31;
    if (l == 0) { ws[w] = s; wq[w] = sq; }
    __syncthreads();
    if (tid == 0) {
        float ts = 0.f, tq = 0.f;
        #pragma unroll
        for (int i = 0; i < 8; i++) { ts += ws[i]; tq += wq[i]; }
        ws[0] = ts; wq[0] = tq;
    }
    __syncthreads();
    const float mu  = ws[0] * (1.f / D_MODEL);
    const float var = wq[0] * (1.f / D_MODEL) - mu * mu;
    const float rs  = rsqrtf(var + 1e-3f);
    const float4 g  = ((const float4*)gamma)[tid];
    const float4 be = ((const float4*)beta)[tid];
    const __half2 h01 = __floats2half2_rn((v.x - mu) * rs * g.x + be.x,
                                          (v.y - mu) * rs * g.y + be.y);
    const __half2 h23 = __floats2half2_rn((v.z - mu) * rs * g.z + be.z,
                                          (v.w - mu) * rs * g.w + be.w);
    uint2 o; o.x = h2u(h01); o.y = h2u(h23);
    ((uint2*)(out + (size_t)row * D_MODEL))[tid] = o;
}

// ------------------------------------------------ FP16 mma.sync GEMM --------
// CTA 128x128, BK=64, 4 warps (2x2), warp tile 64x64. 3-stage cp.async,
// ldmatrix, one __syncthreads per iter. smem 110592 B -> 2 CTA/SM.
#define GST 72
#define GS_HALVES (128*GST)
#define GEMM_SMEM_BYTES (6*GS_HALVES*2)   /* 110592 B */
#define GEMM_THREADS 128

__device__ __forceinline__ void g_load_stage(const __half* __restrict__ Ag,
                                             const __half* __restrict__ Bg,
                                             int K, uint32_t aBase, uint32_t bBase,
                                             int k0, int tid) {
    #pragma unroll
    for (int p = 0; p < 8; p++) {
        const int id = p * GEMM_THREADS + tid;   // 0..1023 : 128 rows x 8 chunks
        const int r = id >> 3, c8 = (id & 7) * 8;
        cp16(aBase + (r * GST + c8) * 2, Ag + (size_t)r * K + k0 + c8);
        cp16(bBase + (r * GST + c8) * 2, Bg + (size_t)r * K + k0 + c8);
    }
    cp_commit();
}

// EPI 0: bias+relu, QKV store (permuted cols [i][h][c]) ;
// EPI 1: bias+relu->half ; EPI 2: bias+residual->f32
template<int EPI>
__global__ void __launch_bounds__(GEMM_THREADS, 2)
mgemm_kernel(const __half* __restrict__ A,
             const __half* __restrict__ WT,
             const float* __restrict__ bias,
             const float* __restrict__ res,
             void* __restrict__ CoutV,
             int M, int N, int K) {
    extern __shared__ __half hsm[];

    const int tid = threadIdx.x;
    const int wid = tid >> 5, lane = tid & 31;
    const int wm = wid & 1, wn = wid >> 1;     // 2 x 2 warp grid, 64x64 tiles
    const int lq = lane >> 2, lr = lane & 3;
    const int bx = blockIdx.x, by = blockIdx.y;

    const __half* Ag = A  + (size_t)(by * 128) * K;
    const __half* Bg = WT + (size_t)(bx * 128) * K;

    uint32_t aBase[3], bBase[3];
    #pragma unroll
    for (int s = 0; s < 3; s++) {
        aBase[s] = smem_u32(hsm + (2 * s)     * GS_HALVES);
        bBase[s] = smem_u32(hsm + (2 * s + 1) * GS_HALVES);
    }

    const int aRow = lane & 15, aK = (lane >> 4) * 8;
    const int bRow = (lane & 7) + ((lane >> 4) << 3), bK = ((lane >> 3) & 1) * 8;

    float acc[4][8][4];
    #pragma unroll
    for (int f = 0; f < 4; f++)
        #pragma unroll
        for (int g = 0; g < 8; g++)
            #pragma unroll
            for (int e = 0; e < 4; e++) acc[f][g][e] = 0.f;

    const int iters = K >> 6;
    g_load_stage(Ag, Bg, K, aBase[0], bBase[0], 0, tid);
    g_load_stage(Ag, Bg, K, aBase[1], bBase[1], 64, tid);

    int s = 0;
    for (int it = 0; it < iters; it++) {
        cp_wait1();
        __syncthreads();
        if (it + 2 < iters) {
            int ns = s + 2; if (ns >= 3) ns -= 3;
            g_load_stage(Ag, Bg, K, aBase[ns], bBase[ns], (it + 2) << 6, tid);
        }

        #pragma unroll
        for (int kk = 0; kk < 4; kk++) {
            const int c0 = kk * 16;
            uint32_t a[4][4], b[8][2];
            #pragma unroll
            for (int f = 0; f < 4; f++)
                ldsm4(a[f], aBase[s] + ((wm * 64 + f * 16 + aRow) * GST + c0 + aK) * 2);
            #pragma unroll
            for (int g2 = 0; g2 < 4; g2++) {
                uint32_t t4[4];
                ldsm4(t4, bBase[s] + ((wn * 64 + g2 * 16 + bRow) * GST + c0 + bK) * 2);
                b[g2 * 2][0] = t4[0];     b[g2 * 2][1] = t4[1];
                b[g2 * 2 + 1][0] = t4[2]; b[g2 * 2 + 1][1] = t4[3];
            }
            #pragma unroll
            for (int f = 0; f < 4; f++)
                #pragma unroll
                for (int g = 0; g < 8; g++)
                    mma16(acc[f][g], a[f], b[g]);
        }
        s = (s == 2) ? 0 : s + 1;
    }

    #pragma unroll
    for (int f = 0; f < 4; f++) {
        #pragma unroll
        for (int g = 0; g < 8; g++) {
            const int row0 = by * 128 + wm * 64 + f * 16 + lq;
            const int col0 = bx * 128 + wn * 64 + g * 8 + lr * 2;
            #pragma unroll
            for (int h = 0; h < 2; h++) {
                const int row = row0 + h * 8;
                float v0 = acc[f][g][h * 2 + 0] + bias[col0];
                float v1 = acc[f][g][h * 2 + 1] + bias[col0 + 1];
                if (EPI == 0) {
                    v0 = fmaxf(v0, 0.f); v1 = fmaxf(v1, 0.f);
                    const int reg = col0 >> 10;          // 0=q 1=k 2=v
                    const int hh  = (col0 >> 7) & 7;
                    const int cc  = col0 & 127;
                    const int bb  = row >> 11;
                    const int nn  = row & 2047;
                    if (reg == 2) {
                        const size_t base =
                            (((size_t)bb * NHEAD + hh) * CHEAD + cc) * SEQ + nn;
                        g_v[base]       = __float2half(v0);
                        g_v[base + SEQ] = __float2half(v1);
                    } else {
                        __half* dptr = reg ? g_k : g_q;
                        const size_t base =
                            (((size_t)bb * NHEAD + hh) * SEQ + nn) * CHEAD + cc;
                        *(__half2*)&dptr[base] = __floats2half2_rn(v0, v1);
                    }
                } else if (EPI == 1) {
                    __half2 o = __floats2half2_rn(fmaxf(v0, 0.f), fmaxf(v1, 0.f));
                    *(__half2*)&((__half*)CoutV)[(size_t)row * N + col0] = o;
                } else {
                    float* Cout = (float*)CoutV;
                    const float2 rr = *(const float2*)&res[(size_t)row * N + col0];
                    float2 o; o.x = v0 + rr.x; o.y = v1 + rr.y;
                    *(float2*)&Cout[(size_t)row * N + col0] = o;
                }
            }
        }
    }
}

// ---------------------------------------- FA2-style fp16 tensor Attention ---
#define AQ_ST 136
#define AV_ST 72
#define ATTN_H   (128*AQ_ST + 64*AQ_ST + 128*AV_ST)
#define ATTN_SMEM_BYTES (ATTN_H*2)   /* 70656 B */

__global__ void __launch_bounds__(256) attn_kernel(const float* __restrict__ x,
                                                   float* __restrict__ out) {
    extern __shared__ __half hsm[];
    __half* sQ  = hsm;                  // [128][136]  (pre-scaled by 0.125)
    __half* sK  = sQ  + 128 * AQ_ST;    // [64][136]
    __half* sVt = sK  + 64  * AQ_ST;    // [128][72]   ([c][kv])

    const int qb = blockIdx.x, h = blockIdx.y, b = blockIdx.z;
    const int tid = threadIdx.x;
    const int wid = tid >> 5, lane = tid & 31;
    const int lq = lane >> 2, lr = lane & 3;

    const uint32_t qB = smem_u32(sQ);
    const uint32_t kB = smem_u32(sK);
    const uint32_t vB = smem_u32(sVt);
    const int aRow = lane & 15, aK = (lane >> 4) * 8;
    const int bRow = (lane & 7) + ((lane >> 4) << 3), bK = ((lane >> 3) & 1) * 8;

    const size_t bh  = ((size_t)b * NHEAD + h) * SEQ;
    const __half* Qg = g_q + (bh + (size_t)qb * 128) * CHEAD;
    const __half* Vb = g_v + ((size_t)b * NHEAD + h) * CHEAD * SEQ;

    const __half2 qscale = __floats2half2_rn(0.125f, 0.125f);
    for (int idx = tid; idx < 128 * 16; idx += 256) {
        const int r = idx >> 4, c8 = (idx & 15) * 8;
        uint4 v = *(const uint4*)&Qg[r * 128 + c8];
        __half2* hv = (__half2*)&v;
        #pragma unroll
        for (int j = 0; j < 4; j++) hv[j] = __hmul2(hv[j], qscale);
        *(uint4*)&sQ[r * AQ_ST + c8] = v;
    }

    float m0 = -1e30f, m1 = -1e30f, l0 = 0.f, l1 = 0.f;
    float oacc[16][4];
    #pragma unroll
    for (int t = 0; t < 16; t++)
        #pragma unroll
        for (int e = 0; e < 4; e++) oacc[t][e] = 0.f;

    for (int kt = 0; kt < SEQ / 64; kt++) {
        __syncthreads();
        const __half* Kg = g_k + (bh + (size_t)kt * 64) * CHEAD;
        for (int idx = tid; idx < 64 * 16; idx += 256) {
            const int r = idx >> 4, c8 = (idx & 15) * 8;
            *(uint4*)&sK[r * AQ_ST + c8] = *(const uint4*)&Kg[r * 128 + c8];
        }
        for (int idx = tid; idx < 128 * 8; idx += 256) {
            const int c = idx >> 3, k8 = (idx & 7) * 8;
            *(uint4*)&sVt[c * AV_ST + k8] =
                *(const uint4*)&Vb[(size_t)c * SEQ + kt * 64 + k8];
        }
        __syncthreads();

        // ---- S = (Q*scale) @ K^T -------------------------------------------
        float sc[8][4];
        #pragma unroll
        for (int g = 0; g < 8; g++)
            #pragma unroll
            for (int e = 0; e < 4; e++) sc[g][e] = 0.f;
        #pragma unroll
        for (int kk = 0; kk < 8; kk++) {
            const int c0 = kk * 16;
            uint32_t a[4], bfr[8][2];
            ldsm4(a, qB + ((wid * 16 + aRow) * AQ_ST + c0 + aK) * 2);
            #pragma unroll
            for (int g4 = 0; g4 < 4; g4++) {
                uint32_t t4[4];
                ldsm4(t4, kB + ((g4 * 16 + bRow) * AQ_ST + c0 + bK) * 2);
                bfr[g4 * 2][0] = t4[0];     bfr[g4 * 2][1] = t4[1];
                bfr[g4 * 2 + 1][0] = t4[2]; bfr[g4 * 2 + 1][1] = t4[3];
            }
            #pragma unroll
            for (int g = 0; g < 8; g++)
                mma16(sc[g], a, bfr[g]);
        }

        // ---- register online softmax ----------------------------------------
        float mx0 = -1e30f, mx1 = -1e30f;
        #pragma unroll
        for (int g = 0; g < 8; g++) {
            mx0 = fmaxf(mx0, fmaxf(sc[g][0], sc[g][1]));
            mx1 = fmaxf(mx1, fmaxf(sc[g][2], sc[g][3]));
        }
        mx0 = fmaxf(mx0, __shfl_xor_sync(0xffffffffu, mx0, 1));
        mx0 = fmaxf(mx0, __shfl_xor_sync(0xffffffffu, mx0, 2));
        mx1 = fmaxf(mx1, __shfl_xor_sync(0xffffffffu, mx1, 1));
        mx1 = fmaxf(mx1, __shfl_xor_sync(0xffffffffu, mx1, 2));
        const float mn0 = fmaxf(m0, mx0), mn1 = fmaxf(m1, mx1);
        const float al0 = __expf(m0 - mn0), al1 = __expf(m1 - mn1);
        m0 = mn0; m1 = mn1;

        uint32_t aP[4][4];
        float sum0 = 0.f, sum1 = 0.f;
        #pragma unroll
        for (int g = 0; g < 8; g++) {
            const float p0 = __expf(sc[g][0] - mn0);
            const float p1 = __expf(sc[g][1] - mn0);
            const float p2 = __expf(sc[g][2] - mn1);
            const float p3 = __expf(sc[g][3] - mn1);
            const __half2 ph01 = __floats2half2_rn(p0, p1);
            const __half2 ph23 = __floats2half2_rn(p2, p3);
            const float2 f01 = __half22float2(ph01);
            const float2 f23 = __half22float2(ph23);
            sum0 += f01.x + f01.y;
            sum1 += f23.x + f23.y;
            const int kk = g >> 1, hi = (g & 1) * 2;
            aP[kk][hi]     = h2u(ph01);
            aP[kk][hi + 1] = h2u(ph23);
        }
        sum0 += __shfl_xor_sync(0xffffffffu, sum0, 1);
        sum0 += __shfl_xor_sync(0xffffffffu, sum0, 2);
        sum1 += __shfl_xor_sync(0xffffffffu, sum1, 1);
        sum1 += __shfl_xor_sync(0xffffffffu, sum1, 2);
        l0 = l0 * al0 + sum0;
        l1 = l1 * al1 + sum1;

        // ---- O = O*alpha + P @ V --------------------------------------------
        #pragma unroll
        for (int t = 0; t < 16; t++) {
            oacc[t][0] *= al0; oacc[t][1] *= al0;
            oacc[t][2] *= al1; oacc[t][3] *= al1;
        }
        #pragma unroll
        for (int kk = 0; kk < 4; kk++) {
            const int c0 = kk * 16;
            uint32_t bfr[16][2];
            #pragma unroll
            for (int f4 = 0; f4 < 8; f4++) {
                uint32_t t4[4];
                ldsm4(t4, vB + ((f4 * 16 + bRow) * AV_ST + c0 + bK) * 2);
                bfr[f4 * 2][0] = t4[0];     bfr[f4 * 2][1] = t4[1];
                bfr[f4 * 2 + 1][0] = t4[2]; bfr[f4 * 2 + 1][1] = t4[3];
            }
            #pragma unroll
            for (int t = 0; t < 16; t++)
                mma16(oacc[t], aP[kk], bfr[t]);
        }
    }

    // ------------------------------ epilogue --------------------------------
    const float inv0 = 1.f / l0, inv1 = 1.f / l1;
    const int q0 = qb * 128 + wid * 16 + lq;
    #pragma unroll
    for (int t = 0; t < 16; t++) {
        const int col = t * 8 + lr * 2;
        const size_t b0 = ((size_t)b * SEQ + q0) * D_MODEL + h * CHEAD + col;
        const size_t b1 = ((size_t)b * SEQ + q0 + 8) * D_MODEL + h * CHEAD + col;
        const float2 x0 = *(const float2*)&x[b0];
        const float2 x1 = *(const float2*)&x[b1];
        float2 o0, o1;
        o0.x = oacc[t][0] * inv0 + x0.x; o0.y = oacc[t][1] * inv0 + x0.y;
        o1.x = oacc[t][2] * inv1 + x1.x; o1.y = oacc[t][3] * inv1 + x1.y;
        *(float2*)&out[b0] = o0;
        *(float2*)&out[b1] = o1;
    }
}

// ------------------------------------------------------------------ launch --
extern "C" void kernel_launch(void* const* d_in, const int* in_sizes, int n_in,
                              void* d_out, int out_size) {
    const float* x    = (const float*)d_in[0];
    const float* ln_g = (const float*)d_in[1];
    const float* ln_b = (const float*)d_in[2];
    const float* w3   = (const float*)d_in[3];
    const float* b3   = (const float*)d_in[4];
    const float* w1   = (const float*)d_in[5];
    const float* b1   = (const float*)d_in[6];
    const float* w2   = (const float*)d_in[7];
    const float* b2   = (const float*)d_in[8];
    float* out = (float*)d_out;

    __half *yh, *h1, *wh;
    float *att, *b3p;
    cudaGetSymbolAddress((void**)&yh,  g_yh);
    cudaGetSymbolAddress((void**)&att, g_att);
    cudaGetSymbolAddress((void**)&h1,  g_h1);
    cudaGetSymbolAddress((void**)&wh,  g_wh);
    cudaGetSymbolAddress((void**)&b3p, g_b3p);

    cudaFuncSetAttribute(attn_kernel, cudaFuncAttributeMaxDynamicSharedMemorySize,
                         ATTN_SMEM_BYTES);
    cudaFuncSetAttribute(mgemm_kernel<0>, cudaFuncAttributeMaxDynamicSharedMemorySize,
                         GEMM_SMEM_BYTES);
    cudaFuncSetAttribute(mgemm_kernel<1>, cudaFuncAttributeMaxDynamicSharedMemorySize,
                         GEMM_SMEM_BYTES);
    cudaFuncSetAttribute(mgemm_kernel<2>, cudaFuncAttributeMaxDynamicSharedMemorySize,
                         GEMM_SMEM_BYTES);

    tc_qkv_kernel<<<dim3(3072/32, 1024/32), dim3(32, 8)>>>(w3, wh + WH3_OFF, 1024, 3072);
    tc_kernel<<<dim3(4096/32, 1024/32), dim3(32, 8)>>>(w1, wh + WH1_OFF, 1024, 4096);
    tc_kernel<<<dim3(1024/32, 4096/32), dim3(32, 8)>>>(w2, wh + WH2_OFF, 4096, 1024);
    permb_kernel<<<12, 256>>>(b3, b3p);

    ln_kernel<<<ROWS, 256>>>(x, ln_g, ln_b, yh);
    mgemm_kernel<0><<<dim3(3072/128, ROWS/128), GEMM_THREADS, GEMM_SMEM_BYTES>>>(
        yh, wh + WH3_OFF, b3p, nullptr, nullptr, ROWS, 3072, 1024);
    attn_kernel<<<dim3(SEQ/128, NHEAD, BATCH), 256, ATTN_SMEM_BYTES>>>(x, att);
    ln_kernel<<<ROWS, 256>>>(att, ln_g, ln_b, yh);
    mgemm_kernel<1><<<dim3(4096/128, ROWS/128), GEMM_THREADS, GEMM_SMEM_BYTES>>>(
        yh, wh + WH1_OFF, b1, nullptr, h1, ROWS, 4096, 1024);
    mgemm_kernel<2><<<dim3(1024/128, ROWS/128), GEMM_THREADS, GEMM_SMEM_BYTES>>>(
        h1, wh + WH2_OFF, b2, att, out, ROWS, 1024, 4096);
}

// round 15
// speedup vs baseline: 1.7392x; 1.1204x over previous
#include <cuda_runtime.h>
#include <cuda_fp16.h>
#include <math.h>
#include <stdint.h>

#define D_MODEL 1024
#define NHEAD 8
#define CHEAD 128
#define BATCH 4
#define SEQ 2048
#define ROWS (BATCH*SEQ)   /* 8192 */

// ---------------- scratch (module-static device memory; no runtime allocs) ---
__device__ __align__(128) __half g_yh [ROWS * D_MODEL];
__device__ __align__(128) __half g_q  [BATCH * NHEAD * SEQ * CHEAD]; // [b][h][n][c]
__device__ __align__(128) __half g_k  [BATCH * NHEAD * SEQ * CHEAD]; // [b][h][n][c]
__device__ __align__(128) __half g_v  [BATCH * NHEAD * CHEAD * SEQ]; // [b][h][c][n]
__device__ __align__(128) float  g_att[ROWS * D_MODEL];
__device__ __align__(128) __half g_h1 [ROWS * 4 * D_MODEL];
__device__ __align__(128) float  g_b3p[3 * D_MODEL];                 // permuted b3
#define WH3_OFF 0
#define WH1_OFF (3072*1024)
#define WH2_OFF (WH1_OFF + 4096*1024)
__device__ __align__(128) __half g_wh [WH2_OFF + 1024*4096];

// ------------------------------------------------------------ PTX helpers ---
__device__ __forceinline__ uint32_t smem_u32(const void* p) {
    uint32_t r;
    asm("{ .reg .u64 t; cvta.to.shared.u64 t, %1; cvt.u32.u64 %0, t; }"
        : "=r"(r) : "l"(p));
    return r;
}
__device__ __forceinline__ void cp16(uint32_t dst, const void* src) {
    asm volatile("cp.async.ca.shared.global [%0], [%1], 16;\n" :: "r"(dst), "l"(src));
}
__device__ __forceinline__ void cp_commit() {
    asm volatile("cp.async.commit_group;\n" ::: "memory");
}
__device__ __forceinline__ void cp_wait1() {
    asm volatile("cp.async.wait_group 1;\n" ::: "memory");
}
__device__ __forceinline__ void cp_wait0() {
    asm volatile("cp.async.wait_group 0;\n" ::: "memory");
}
__device__ __forceinline__ void ldsm4(uint32_t* r, uint32_t addr) {
    asm volatile("ldmatrix.sync.aligned.m8n8.x4.shared.b16 {%0,%1,%2,%3}, [%4];"
        : "=r"(r[0]), "=r"(r[1]), "=r"(r[2]), "=r"(r[3]) : "r"(addr));
}
__device__ __forceinline__ void mma16(float* c, const uint32_t* a, const uint32_t* b) {
    asm volatile(
        "mma.sync.aligned.m16n8k16.row.col.f32.f16.f16.f32 "
        "{%0,%1,%2,%3}, {%4,%5,%6,%7}, {%8,%9}, {%0,%1,%2,%3};"
        : "+f"(c[0]), "+f"(c[1]), "+f"(c[2]), "+f"(c[3])
        : "r"(a[0]), "r"(a[1]), "r"(a[2]), "r"(a[3]), "r"(b[0]), "r"(b[1]));
}
__device__ __forceinline__ uint32_t h2u(__half2 h) {
    return *(uint32_t*)&h;
}

// ------------------------------------------- weight transpose+convert -------
__global__ void __launch_bounds__(256) tc_kernel(const float* __restrict__ in,
                                                 __half* __restrict__ out,
                                                 int K, int N) {
    __shared__ float t[32][33];
    const int nb = blockIdx.x * 32, kb = blockIdx.y * 32;
    const int tx = threadIdx.x, ty = threadIdx.y;
    #pragma unroll
    for (int i = 0; i < 32; i += 8)
        t[ty + i][tx] = in[(size_t)(kb + ty + i) * N + nb + tx];
    __syncthreads();
    #pragma unroll
    for (int i = 0; i < 32; i += 8)
        out[(size_t)(nb + ty + i) * K + kb + tx] = __float2half(t[tx][ty + i]);
}

// w3 variant: output ROW index permuted  n=(c*24+h*3+i) -> n'=i*1024+h*128+c
__global__ void __launch_bounds__(256) tc_qkv_kernel(const float* __restrict__ in,
                                                     __half* __restrict__ out,
                                                     int K, int N) {
    __shared__ float t[32][33];
    const int nb = blockIdx.x * 32, kb = blockIdx.y * 32;
    const int tx = threadIdx.x, ty = threadIdx.y;
    #pragma unroll
    for (int i = 0; i < 32; i += 8)
        t[ty + i][tx] = in[(size_t)(kb + ty + i) * N + nb + tx];
    __syncthreads();
    #pragma unroll
    for (int i = 0; i < 32; i += 8) {
        const int n  = nb + ty + i;
        const int c  = n / 24;
        const int rm = n - c * 24;
        const int hh = rm / 3;
        const int ii = rm - hh * 3;
        const size_t np = (size_t)ii * 1024 + hh * 128 + c;
        out[np * K + kb + tx] = __float2half(t[tx][ty + i]);
    }
}

__global__ void __launch_bounds__(256) permb_kernel(const float* __restrict__ in,
                                                    float* __restrict__ out) {
    const int n = blockIdx.x * 256 + threadIdx.x;
    if (n < 3 * D_MODEL) {
        const int c  = n / 24;
        const int rm = n - c * 24;
        const int hh = rm / 3;
        const int ii = rm - hh * 3;
        out[ii * 1024 + hh * 128 + c] = in[n];
    }
}

// ---------------------------------------------------------------- LayerNorm --
__global__ void __launch_bounds__(256) ln_kernel(const float* __restrict__ in,
                                                 const float* __restrict__ gamma,
                                                 const float* __restrict__ beta,
                                                 __half* __restrict__ out) {
    const int row = blockIdx.x;
    const int tid = threadIdx.x;
    const float4 v = ((const float4*)(in + (size_t)row * D_MODEL))[tid];
    float s  = v.x + v.y + v.z + v.w;
    float sq = v.x * v.x + v.y * v.y + v.z * v.z + v.w * v.w;
    #pragma unroll
    for (int o = 16; o; o >>= 1) {
        s  += __shfl_xor_sync(0xffffffffu, s,  o);
        sq += __shfl_xor_sync(0xffffffffu, sq, o);
    }
    __shared__ float ws[8], wq[8];
    const int w = tid >> 5, l = tid & 31;
    if (l == 0) { ws[w] = s; wq[w] = sq; }
    __syncthreads();
    if (tid == 0) {
        float ts = 0.f, tq = 0.f;
        #pragma unroll
        for (int i = 0; i < 8; i++) { ts += ws[i]; tq += wq[i]; }
        ws[0] = ts; wq[0] = tq;
    }
    __syncthreads();
    const float mu  = ws[0] * (1.f / D_MODEL);
    const float var = wq[0] * (1.f / D_MODEL) - mu * mu;
    const float rs  = rsqrtf(var + 1e-3f);
    const float4 g  = ((const float4*)gamma)[tid];
    const float4 be = ((const float4*)beta)[tid];
    const __half2 h01 = __floats2half2_rn((v.x - mu) * rs * g.x + be.x,
                                          (v.y - mu) * rs * g.y + be.y);
    const __half2 h23 = __floats2half2_rn((v.z - mu) * rs * g.z + be.z,
                                          (v.w - mu) * rs * g.w + be.w);
    uint2 o; o.x = h2u(h01); o.y = h2u(h23);
    ((uint2*)(out + (size_t)row * D_MODEL))[tid] = o;
}

// ------------------------------------------------ FP16 mma.sync GEMM --------
// CTA 128x128, BK=64, 4 warps (2x2), warp tile 64x64. 3-stage cp.async,
// ldmatrix with kk-level fragment double buffering, one barrier per iter.
#define GST 72
#define GS_HALVES (128*GST)
#define GEMM_SMEM_BYTES (6*GS_HALVES*2)   /* 110592 B */
#define GEMM_THREADS 128

__device__ __forceinline__ void g_load_stage(const __half* __restrict__ Ag,
                                             const __half* __restrict__ Bg,
                                             int K, uint32_t aBase, uint32_t bBase,
                                             int k0, int tid) {
    #pragma unroll
    for (int p = 0; p < 8; p++) {
        const int id = p * GEMM_THREADS + tid;
        const int r = id >> 3, c8 = (id & 7) * 8;
        cp16(aBase + (r * GST + c8) * 2, Ag + (size_t)r * K + k0 + c8);
        cp16(bBase + (r * GST + c8) * 2, Bg + (size_t)r * K + k0 + c8);
    }
    cp_commit();
}

template<int EPI>
__global__ void __launch_bounds__(GEMM_THREADS, 2)
mgemm_kernel(const __half* __restrict__ A,
             const __half* __restrict__ WT,
             const float* __restrict__ bias,
             const float* __restrict__ res,
             void* __restrict__ CoutV,
             int M, int N, int K) {
    extern __shared__ __half hsm[];

    const int tid = threadIdx.x;
    const int wid = tid >> 5, lane = tid & 31;
    const int wm = wid & 1, wn = wid >> 1;     // 2 x 2 warp grid, 64x64 tiles
    const int lq = lane >> 2, lr = lane & 3;
    const int bx = blockIdx.x, by = blockIdx.y;

    const __half* Ag = A  + (size_t)(by * 128) * K;
    const __half* Bg = WT + (size_t)(bx * 128) * K;

    uint32_t aBase[3], bBase[3];
    #pragma unroll
    for (int s = 0; s < 3; s++) {
        aBase[s] = smem_u32(hsm + (2 * s)     * GS_HALVES);
        bBase[s] = smem_u32(hsm + (2 * s + 1) * GS_HALVES);
    }

    const int aRow = lane & 15, aK = (lane >> 4) * 8;
    const int bRow = (lane & 7) + ((lane >> 4) << 3), bK = ((lane >> 3) & 1) * 8;

    float acc[4][8][4];
    #pragma unroll
    for (int f = 0; f < 4; f++)
        #pragma unroll
        for (int g = 0; g < 8; g++)
            #pragma unroll
            for (int e = 0; e < 4; e++) acc[f][g][e] = 0.f;

    const int iters = K >> 6;
    g_load_stage(Ag, Bg, K, aBase[0], bBase[0], 0, tid);
    g_load_stage(Ag, Bg, K, aBase[1], bBase[1], 64, tid);

    uint32_t a[2][4][4], b[2][8][2];

    int s = 0;
    for (int it = 0; it < iters; it++) {
        cp_wait1();
        __syncthreads();
        if (it + 2 < iters) {
            int ns = s + 2; if (ns >= 3) ns -= 3;
            g_load_stage(Ag, Bg, K, aBase[ns], bBase[ns], (it + 2) << 6, tid);
        }

        // preload fragments for kk=0
        {
            #pragma unroll
            for (int f = 0; f < 4; f++)
                ldsm4(a[0][f], aBase[s] + ((wm * 64 + f * 16 + aRow) * GST + aK) * 2);
            #pragma unroll
            for (int g2 = 0; g2 < 4; g2++) {
                uint32_t t4[4];
                ldsm4(t4, bBase[s] + ((wn * 64 + g2 * 16 + bRow) * GST + bK) * 2);
                b[0][g2 * 2][0] = t4[0];     b[0][g2 * 2][1] = t4[1];
                b[0][g2 * 2 + 1][0] = t4[2]; b[0][g2 * 2 + 1][1] = t4[3];
            }
        }

        #pragma unroll
        for (int kk = 0; kk < 4; kk++) {
            const int cur = kk & 1, nxt = cur ^ 1;
            if (kk < 3) {
                const int c0 = (kk + 1) * 16;
                #pragma unroll
                for (int f = 0; f < 4; f++)
                    ldsm4(a[nxt][f],
                          aBase[s] + ((wm * 64 + f * 16 + aRow) * GST + c0 + aK) * 2);
                #pragma unroll
                for (int g2 = 0; g2 < 4; g2++) {
                    uint32_t t4[4];
                    ldsm4(t4, bBase[s] + ((wn * 64 + g2 * 16 + bRow) * GST + c0 + bK) * 2);
                    b[nxt][g2 * 2][0] = t4[0];     b[nxt][g2 * 2][1] = t4[1];
                    b[nxt][g2 * 2 + 1][0] = t4[2]; b[nxt][g2 * 2 + 1][1] = t4[3];
                }
            }
            #pragma unroll
            for (int f = 0; f < 4; f++)
                #pragma unroll
                for (int g = 0; g < 8; g++)
                    mma16(acc[f][g], a[cur][f], b[cur][g]);
        }
        s = (s == 2) ? 0 : s + 1;
    }

    #pragma unroll
    for (int f = 0; f < 4; f++) {
        #pragma unroll
        for (int g = 0; g < 8; g++) {
            const int row0 = by * 128 + wm * 64 + f * 16 + lq;
            const int col0 = bx * 128 + wn * 64 + g * 8 + lr * 2;
            #pragma unroll
            for (int h = 0; h < 2; h++) {
                const int row = row0 + h * 8;
                float v0 = acc[f][g][h * 2 + 0] + bias[col0];
                float v1 = acc[f][g][h * 2 + 1] + bias[col0 + 1];
                if (EPI == 0) {
                    v0 = fmaxf(v0, 0.f); v1 = fmaxf(v1, 0.f);
                    const int reg = col0 >> 10;          // 0=q 1=k 2=v
                    const int hh  = (col0 >> 7) & 7;
                    const int cc  = col0 & 127;
                    const int bb  = row >> 11;
                    const int nn  = row & 2047;
                    if (reg == 2) {
                        const size_t base =
                            (((size_t)bb * NHEAD + hh) * CHEAD + cc) * SEQ + nn;
                        g_v[base]       = __float2half(v0);
                        g_v[base + SEQ] = __float2half(v1);
                    } else {
                        __half* dptr = reg ? g_k : g_q;
                        const size_t base =
                            (((size_t)bb * NHEAD + hh) * SEQ + nn) * CHEAD + cc;
                        *(__half2*)&dptr[base] = __floats2half2_rn(v0, v1);
                    }
                } else if (EPI == 1) {
                    __half2 o = __floats2half2_rn(fmaxf(v0, 0.f), fmaxf(v1, 0.f));
                    *(__half2*)&((__half*)CoutV)[(size_t)row * N + col0] = o;
                } else {
                    float* Cout = (float*)CoutV;
                    const float2 rr = *(const float2*)&res[(size_t)row * N + col0];
                    float2 o; o.x = v0 + rr.x; o.y = v1 + rr.y;
                    *(float2*)&Cout[(size_t)row * N + col0] = o;
                }
            }
        }
    }
}

// ---------------------------------------- FA2-style fp16 tensor Attention ---
// Q-tile 128/CTA, KV-tile 64, cp.async double-buffered K/V (prefetch kt+1
// during compute of kt). Softmax in registers; P packed straight to A-frags.
#define AQ_ST 136
#define AV_ST 72
#define KBUF_H (64*AQ_ST)
#define VBUF_H (128*AV_ST)
#define ATTN_H   (128*AQ_ST + 2*KBUF_H + 2*VBUF_H)
#define ATTN_SMEM_BYTES (ATTN_H*2)   /* 106496 B */

__global__ void __launch_bounds__(256) attn_kernel(const float* __restrict__ x,
                                                   float* __restrict__ out) {
    extern __shared__ __half hsm[];
    __half* sQ  = hsm;                         // [128][136] (pre-scaled)
    __half* sK  = sQ  + 128 * AQ_ST;           // [2][64][136]
    __half* sVt = sK  + 2 * KBUF_H;            // [2][128][72]

    const int qb = blockIdx.x, h = blockIdx.y, b = blockIdx.z;
    const int tid = threadIdx.x;
    const int wid = tid >> 5, lane = tid & 31;
    const int lq = lane >> 2, lr = lane & 3;

    const uint32_t qB  = smem_u32(sQ);
    const uint32_t kB0 = smem_u32(sK);
    const uint32_t vB0 = smem_u32(sVt);
    const int aRow = lane & 15, aK = (lane >> 4) * 8;
    const int bRow = (lane & 7) + ((lane >> 4) << 3), bK = ((lane >> 3) & 1) * 8;

    const size_t bh  = ((size_t)b * NHEAD + h) * SEQ;
    const __half* Qg = g_q + (bh + (size_t)qb * 128) * CHEAD;
    const __half* Kb = g_k + bh * CHEAD;
    const __half* Vb = g_v + ((size_t)b * NHEAD + h) * CHEAD * SEQ;

    // per-thread cp.async indices: K 4 chunks, V 4 chunks
    const int kr = tid >> 1,        kc8 = (tid & 1) * 16;   // rows 0..127? no:
    // K tile: 64 rows x 16 chunks = 1024 chunks, 4/thread
    // V tile: 128 rows x 8 chunks = 1024 chunks, 4/thread
    auto issue_kv = [&](int kt, int buf) {
        const __half* Kg = Kb + (size_t)kt * 64 * CHEAD;
        const uint32_t kBase = kB0 + buf * KBUF_H * 2;
        const uint32_t vBase = vB0 + buf * VBUF_H * 2;
        #pragma unroll
        for (int p = 0; p < 4; p++) {
            const int id = p * 256 + tid;            // 0..1023
            const int r = id >> 4, c8 = (id & 15) * 8;
            cp16(kBase + (r * AQ_ST + c8) * 2, Kg + r * 128 + c8);
            const int vc = id >> 3, vk8 = (id & 7) * 8;
            cp16(vBase + (vc * AV_ST + vk8) * 2,
                 Vb + (size_t)vc * SEQ + kt * 64 + vk8);
        }
        cp_commit();
    };

    const __half2 qscale = __floats2half2_rn(0.125f, 0.125f);
    for (int idx = tid; idx < 128 * 16; idx += 256) {
        const int r = idx >> 4, c8 = (idx & 15) * 8;
        uint4 v = *(const uint4*)&Qg[r * 128 + c8];
        __half2* hv = (__half2*)&v;
        #pragma unroll
        for (int j = 0; j < 4; j++) hv[j] = __hmul2(hv[j], qscale);
        *(uint4*)&sQ[r * AQ_ST + c8] = v;
    }

    float m0 = -1e30f, m1 = -1e30f, l0 = 0.f, l1 = 0.f;
    float oacc[16][4];
    #pragma unroll
    for (int t = 0; t < 16; t++)
        #pragma unroll
        for (int e = 0; e < 4; e++) oacc[t][e] = 0.f;

    issue_kv(0, 0);

    const int NT = SEQ / 64;
    for (int kt = 0; kt < NT; kt++) {
        const int buf = kt & 1;
        cp_wait0();
        __syncthreads();
        if (kt + 1 < NT) issue_kv(kt + 1, buf ^ 1);

        const uint32_t kB = kB0 + buf * KBUF_H * 2;
        const uint32_t vB = vB0 + buf * VBUF_H * 2;

        // ---- S = (Q*scale) @ K^T -------------------------------------------
        float sc[8][4];
        #pragma unroll
        for (int g = 0; g < 8; g++)
            #pragma unroll
            for (int e = 0; e < 4; e++) sc[g][e] = 0.f;
        #pragma unroll
        for (int kk = 0; kk < 8; kk++) {
            const int c0 = kk * 16;
            uint32_t a[4], bfr[8][2];
            ldsm4(a, qB + ((wid * 16 + aRow) * AQ_ST + c0 + aK) * 2);
            #pragma unroll
            for (int g4 = 0; g4 < 4; g4++) {
                uint32_t t4[4];
                ldsm4(t4, kB + ((g4 * 16 + bRow) * AQ_ST + c0 + bK) * 2);
                bfr[g4 * 2][0] = t4[0];     bfr[g4 * 2][1] = t4[1];
                bfr[g4 * 2 + 1][0] = t4[2]; bfr[g4 * 2 + 1][1] = t4[3];
            }
            #pragma unroll
            for (int g = 0; g < 8; g++)
                mma16(sc[g], a, bfr[g]);
        }

        // ---- register online softmax ----------------------------------------
        float mx0 = -1e30f, mx1 = -1e30f;
        #pragma unroll
        for (int g = 0; g < 8; g++) {
            mx0 = fmaxf(mx0, fmaxf(sc[g][0], sc[g][1]));
            mx1 = fmaxf(mx1, fmaxf(sc[g][2], sc[g][3]));
        }
        mx0 = fmaxf(mx0, __shfl_xor_sync(0xffffffffu, mx0, 1));
        mx0 = fmaxf(mx0, __shfl_xor_sync(0xffffffffu, mx0, 2));
        mx1 = fmaxf(mx1, __shfl_xor_sync(0xffffffffu, mx1, 1));
        mx1 = fmaxf(mx1, __shfl_xor_sync(0xffffffffu, mx1, 2));
        const float mn0 = fmaxf(m0, mx0), mn1 = fmaxf(m1, mx1);
        const float al0 = __expf(m0 - mn0), al1 = __expf(m1 - mn1);
        m0 = mn0; m1 = mn1;

        uint32_t aP[4][4];
        float sum0 = 0.f, sum1 = 0.f;
        #pragma unroll
        for (int g = 0; g < 8; g++) {
            const float p0 = __expf(sc[g][0] - mn0);
            const float p1 = __expf(sc[g][1] - mn0);
            const float p2 = __expf(sc[g][2] - mn1);
            const float p3 = __expf(sc[g][3] - mn1);
            const __half2 ph01 = __floats2half2_rn(p0, p1);
            const __half2 ph23 = __floats2half2_rn(p2, p3);
            const float2 f01 = __half22float2(ph01);
            const float2 f23 = __half22float2(ph23);
            sum0 += f01.x + f01.y;
            sum1 += f23.x + f23.y;
            const int kk = g >> 1, hi = (g & 1) * 2;
            aP[kk][hi]     = h2u(ph01);
            aP[kk][hi + 1] = h2u(ph23);
        }
        sum0 += __shfl_xor_sync(0xffffffffu, sum0, 1);
        sum0 += __shfl_xor_sync(0xffffffffu, sum0, 2);
        sum1 += __shfl_xor_sync(0xffffffffu, sum1, 1);
        sum1 += __shfl_xor_sync(0xffffffffu, sum1, 2);
        l0 = l0 * al0 + sum0;
        l1 = l1 * al1 + sum1;

        // ---- O = O*alpha + P @ V --------------------------------------------
        #pragma unroll
        for (int t = 0; t < 16; t++) {
            oacc[t][0] *= al0; oacc[t][1] *= al0;
            oacc[t][2] *= al1; oacc[t][3] *= al1;
        }
        #pragma unroll
        for (int kk = 0; kk < 4; kk++) {
            const int c0 = kk * 16;
            uint32_t bfr[16][2];
            #pragma unroll
            for (int f4 = 0; f4 < 8; f4++) {
                uint32_t t4[4];
                ldsm4(t4, vB + ((f4 * 16 + bRow) * AV_ST + c0 + bK) * 2);
                bfr[f4 * 2][0] = t4[0];     bfr[f4 * 2][1] = t4[1];
                bfr[f4 * 2 + 1][0] = t4[2]; bfr[f4 * 2 + 1][1] = t4[3];
            }
            #pragma unroll
            for (int t = 0; t < 16; t++)
                mma16(oacc[t], aP[kk], bfr[t]);
        }
    }

    // ------------------------------ epilogue --------------------------------
    const float inv0 = 1.f / l0, inv1 = 1.f / l1;
    const int q0 = qb * 128 + wid * 16 + lq;
    #pragma unroll
    for (int t = 0; t < 16; t++) {
        const int col = t * 8 + lr * 2;
        const size_t b0 = ((size_t)b * SEQ + q0) * D_MODEL + h * CHEAD + col;
        const size_t b1 = ((size_t)b * SEQ + q0 + 8) * D_MODEL + h * CHEAD + col;
        const float2 x0 = *(const float2*)&x[b0];
        const float2 x1 = *(const float2*)&x[b1];
        float2 o0, o1;
        o0.x = oacc[t][0] * inv0 + x0.x; o0.y = oacc[t][1] * inv0 + x0.y;
        o1.x = oacc[t][2] * inv1 + x1.x; o1.y = oacc[t][3] * inv1 + x1.y;
        *(float2*)&out[b0] = o0;
        *(float2*)&out[b1] = o1;
    }
}

// ------------------------------------------------------------------ launch --
extern "C" void kernel_launch(void* const* d_in, const int* in_sizes, int n_in,
                              void* d_out, int out_size) {
    const float* x    = (const float*)d_in[0];
    const float* ln_g = (const float*)d_in[1];
    const float* ln_b = (const float*)d_in[2];
    const float* w3   = (const float*)d_in[3];
    const float* b3   = (const float*)d_in[4];
    const float* w1   = (const float*)d_in[5];
    const float* b1   = (const float*)d_in[6];
    const float* w2   = (const float*)d_in[7];
    const float* b2   = (const float*)d_in[8];
    float* out = (float*)d_out;

    __half *yh, *h1, *wh;
    float *att, *b3p;
    cudaGetSymbolAddress((void**)&yh,  g_yh);
    cudaGetSymbolAddress((void**)&att, g_att);
    cudaGetSymbolAddress((void**)&h1,  g_h1);
    cudaGetSymbolAddress((void**)&wh,  g_wh);
    cudaGetSymbolAddress((void**)&b3p, g_b3p);

    cudaFuncSetAttribute(attn_kernel, cudaFuncAttributeMaxDynamicSharedMemorySize,
                         ATTN_SMEM_BYTES);
    cudaFuncSetAttribute(mgemm_kernel<0>, cudaFuncAttributeMaxDynamicSharedMemorySize,
                         GEMM_SMEM_BYTES);
    cudaFuncSetAttribute(mgemm_kernel<1>, cudaFuncAttributeMaxDynamicSharedMemorySize,
                         GEMM_SMEM_BYTES);
    cudaFuncSetAttribute(mgemm_kernel<2>, cudaFuncAttributeMaxDynamicSharedMemorySize,
                         GEMM_SMEM_BYTES);

    tc_qkv_kernel<<<dim3(3072/32, 1024/32), dim3(32, 8)>>>(w3, wh + WH3_OFF, 1024, 3072);
    tc_kernel<<<dim3(4096/32, 1024/32), dim3(32, 8)>>>(w1, wh + WH1_OFF, 1024, 4096);
    tc_kernel<<<dim3(1024/32, 4096/32), dim3(32, 8)>>>(w2, wh + WH2_OFF, 4096, 1024);
    permb_kernel<<<12, 256>>>(b3, b3p);

    ln_kernel<<<ROWS, 256>>>(x, ln_g, ln_b, yh);
    mgemm_kernel<0><<<dim3(3072/128, ROWS/128), GEMM_THREADS, GEMM_SMEM_BYTES>>>(
        yh, wh + WH3_OFF, b3p, nullptr, nullptr, ROWS, 3072, 1024);
    attn_kernel<<<dim3(SEQ/128, NHEAD, BATCH), 256, ATTN_SMEM_BYTES>>>(x, att);
    ln_kernel<<<ROWS, 256>>>(att, ln_g, ln_b, yh);
    mgemm_kernel<1><<<dim3(4096/128, ROWS/128), GEMM_THREADS, GEMM_SMEM_BYTES>>>(
        yh, wh + WH1_OFF, b1, nullptr, h1, ROWS, 4096, 1024);
    mgemm_kernel<2><<<dim3(1024/128, ROWS/128), GEMM_THREADS, GEMM_SMEM_BYTES>>>(
        h1, wh + WH2_OFF, b2, att, out, ROWS, 1024, 4096);
}